// round 1
// baseline (speedup 1.0000x reference)
#include <cuda_runtime.h>
#include <math.h>
#include <stdint.h>

// ---------------- problem constants ----------------
#define BT_   4096          // B*T
#define C_    2048
#define T_    1024
#define H_    16
#define HD_   128
#define HID_  5464
#define HIDP_ 5504          // padded hidden (43*128, also /16 for GEMM K)

// ---------------- scratch (device globals, no allocs) ----------------
__device__ float g_Wq[C_*C_];
__device__ float g_Wk[C_*C_];
__device__ float g_Wv[C_*C_];
__device__ float g_Wo[C_*C_];
__device__ float g_Wg[HIDP_*C_];
__device__ float g_Wu[HIDP_*C_];
__device__ float g_Wd[C_*HIDP_];
__device__ float g_xn[BT_*C_];
__device__ float g_q[BT_*C_];
__device__ float g_kk[BT_*C_];
__device__ float g_v[BT_*C_];
__device__ float g_y[BT_*C_];
__device__ float g_h[BT_*C_];
__device__ float g_hn[BT_*C_];
__device__ float g_gate[(size_t)BT_*HIDP_];
__device__ float g_up[(size_t)BT_*HIDP_];
__device__ float g_prod[(size_t)BT_*HIDP_];
__device__ int   g_Ji[64];     // Jinv[k][j] -> i
__device__ float g_Sg[64];     // sign[k][j]
__device__ float g_scale[56];  // 8 scales per weight tensor, 7 tensors

// ---------------- octonion table (replicates reference exactly) ----------------
__global__ void build_tables_k() {
    int   idx[8][8];
    float sg [8][8];
    for (int j = 0; j < 8; j++) { idx[0][j] = j; sg[0][j] = 1.f; }
    for (int i = 1; i < 8; i++) {
        idx[i][0] = i; sg[i][0] = 1.f;
        idx[i][i] = 0; sg[i][i] = -1.f;
    }
    const int tr[7][3] = {{1,2,3},{1,4,5},{1,7,6},{2,4,6},{2,5,7},{3,4,7},{3,6,5}};
    for (int t = 0; t < 7; t++) {
        int a = tr[t][0], b = tr[t][1], c = tr[t][2];
        int per[3][3] = {{a,b,c},{b,c,a},{c,a,b}};
        for (int u = 0; u < 3; u++) {
            int p = per[u][0], q = per[u][1], r = per[u][2];
            idx[p][q] = r; sg[p][q] = 1.f;
            idx[q][p] = r; sg[q][p] = -1.f;
        }
    }
    // out_k gets contribution from input block j = idx-row mapping:
    // xm[i] = SG[k,i] * xp[J[k,i]] with J[k,i]=j, SG[k,i]=sg[i][j] where k=idx[i][j]
    for (int i = 0; i < 8; i++)
        for (int j = 0; j < 8; j++) {
            int k = idx[i][j];
            g_Ji[k*8 + j] = i;
            g_Sg[k*8 + j] = sg[i][j];
        }
}

// ---------------- per-tensor ternary scales: mean(|W|) over (O*P) ----------------
__global__ void compute_scales_k(const float* __restrict__ W, int OP, float* __restrict__ out) {
    int i = blockIdx.x;
    const float* Wi = W + (size_t)i * OP;
    double s = 0.0;
    for (int t = threadIdx.x; t < OP; t += 256) s += (double)fabsf(Wi[t]);
    __shared__ double red[256];
    red[threadIdx.x] = s; __syncthreads();
    for (int st = 128; st > 0; st >>= 1) {
        if (threadIdx.x < st) red[threadIdx.x] += red[threadIdx.x + st];
        __syncthreads();
    }
    if (threadIdx.x == 0) out[i] = (float)(red[0] / (double)OP);
}

__device__ __forceinline__ float tquant(float w, float s) {
    float q = rintf(w / (s + 1e-8f));       // round half-to-even, same as jnp.round
    q = fmaxf(-1.f, fminf(1.f, q));
    return q * s;
}

// full [2048][2048] from W(8,256,256)
__global__ void build_full_sq_k(const float* __restrict__ W, const float* __restrict__ sc,
                                float* __restrict__ F) {
    int id = blockIdx.x * 256 + threadIdx.x;
    int r = id >> 11, c = id & 2047;
    int kb = r >> 8, o = r & 255, jb = c >> 8, p = c & 255;
    int i = g_Ji[kb*8 + jb];
    float s = sc[i];
    float w = W[((size_t)i << 16) + (o << 8) + p];
    F[id] = g_Sg[kb*8 + jb] * tquant(w, s);
}

// full [HIDP][2048] from W(8,683,256) (rows >= 5464 zero)
__global__ void build_full_h_k(const float* __restrict__ W, const float* __restrict__ sc,
                               float* __restrict__ F) {
    int id = blockIdx.x * 256 + threadIdx.x;
    int r = id >> 11, c = id & 2047;
    if (r >= HID_) { F[id] = 0.f; return; }
    int kb = r / 683, o = r - kb * 683;
    int jb = c >> 8, p = c & 255;
    int i = g_Ji[kb*8 + jb];
    float s = sc[i];
    float w = W[((size_t)i * 683 + o) * 256 + p];
    F[id] = g_Sg[kb*8 + jb] * tquant(w, s);
}

// full [2048][HIDP] from W(8,256,683) (cols >= 5464 zero)
__global__ void build_full_d_k(const float* __restrict__ W, const float* __restrict__ sc,
                               float* __restrict__ F) {
    int id = blockIdx.x * 256 + threadIdx.x;
    int r = id / HIDP_, c = id - r * HIDP_;
    if (c >= HID_) { F[id] = 0.f; return; }
    int kb = r >> 8, o = r & 255;
    int jb = c / 683, p = c - jb * 683;
    int i = g_Ji[kb*8 + jb];
    float s = sc[i];
    float w = W[((size_t)i * 256 + o) * 683 + p];
    F[id] = g_Sg[kb*8 + jb] * tquant(w, s);
}

// ---------------- rmsnorm ----------------
__global__ void rmsnorm_k(const float* __restrict__ x, const float* __restrict__ w,
                          float* __restrict__ out) {
    int row = blockIdx.x;
    const float* xr = x + (size_t)row * C_;
    float s = 0.f;
    for (int c = threadIdx.x; c < C_; c += 256) { float v = xr[c]; s += v * v; }
    __shared__ float red[256];
    red[threadIdx.x] = s; __syncthreads();
    for (int st = 128; st > 0; st >>= 1) {
        if (threadIdx.x < st) red[threadIdx.x] += red[threadIdx.x + st];
        __syncthreads();
    }
    float inv = 1.0f / sqrtf(red[0] / (float)C_ + 1e-6f);
    for (int c = threadIdx.x; c < C_; c += 256)
        out[(size_t)row * C_ + c] = xr[c] * inv * w[c];
}

// ---------------- GEMM: C[M,N] = A[M,K] @ B[N,K]^T (+ optional addsrc) ----------------
// All M multiples of 128, N multiples of 128, K multiples of 16.
__global__ __launch_bounds__(256) void gemm_k(
    const float* __restrict__ A, const float* __restrict__ Bm,
    const float* __restrict__ addsrc, float* __restrict__ Cm,
    int M, int N, int K)
{
    __shared__ float As[16][132];
    __shared__ float Bs[16][132];
    int bm = blockIdx.y * 128, bn = blockIdx.x * 128;
    int tid = threadIdx.x;
    int lr = tid >> 2, lk = (tid & 3) << 2;
    int ty = tid >> 4, tx = tid & 15;

    float acc[8][8];
#pragma unroll
    for (int i = 0; i < 8; i++)
#pragma unroll
        for (int j = 0; j < 8; j++) acc[i][j] = 0.f;

    for (int k0 = 0; k0 < K; k0 += 16) {
        float4 a0 = *(const float4*)&A [(size_t)(bm + lr)      * K + k0 + lk];
        float4 a1 = *(const float4*)&A [(size_t)(bm + lr + 64) * K + k0 + lk];
        float4 b0 = *(const float4*)&Bm[(size_t)(bn + lr)      * K + k0 + lk];
        float4 b1 = *(const float4*)&Bm[(size_t)(bn + lr + 64) * K + k0 + lk];
        __syncthreads();
        As[lk+0][lr] = a0.x; As[lk+1][lr] = a0.y; As[lk+2][lr] = a0.z; As[lk+3][lr] = a0.w;
        As[lk+0][lr+64] = a1.x; As[lk+1][lr+64] = a1.y; As[lk+2][lr+64] = a1.z; As[lk+3][lr+64] = a1.w;
        Bs[lk+0][lr] = b0.x; Bs[lk+1][lr] = b0.y; Bs[lk+2][lr] = b0.z; Bs[lk+3][lr] = b0.w;
        Bs[lk+0][lr+64] = b1.x; Bs[lk+1][lr+64] = b1.y; Bs[lk+2][lr+64] = b1.z; Bs[lk+3][lr+64] = b1.w;
        __syncthreads();
#pragma unroll
        for (int kk = 0; kk < 16; kk++) {
            float4 ra0 = *(const float4*)&As[kk][ty * 4];
            float4 ra1 = *(const float4*)&As[kk][64 + ty * 4];
            float4 rb0 = *(const float4*)&Bs[kk][tx * 4];
            float4 rb1 = *(const float4*)&Bs[kk][64 + tx * 4];
            float ra[8] = {ra0.x, ra0.y, ra0.z, ra0.w, ra1.x, ra1.y, ra1.z, ra1.w};
            float rb[8] = {rb0.x, rb0.y, rb0.z, rb0.w, rb1.x, rb1.y, rb1.z, rb1.w};
#pragma unroll
            for (int i = 0; i < 8; i++)
#pragma unroll
                for (int j = 0; j < 8; j++) acc[i][j] = fmaf(ra[i], rb[j], acc[i][j]);
        }
    }

#pragma unroll
    for (int i = 0; i < 8; i++) {
        int r = bm + ((i < 4) ? (ty * 4 + i) : (64 + ty * 4 + i - 4));
        size_t base = (size_t)r * N + bn;
        float4 v0 = make_float4(acc[i][0], acc[i][1], acc[i][2], acc[i][3]);
        float4 v1 = make_float4(acc[i][4], acc[i][5], acc[i][6], acc[i][7]);
        if (addsrc) {
            float4 s0 = *(const float4*)&addsrc[base + tx * 4];
            float4 s1 = *(const float4*)&addsrc[base + 64 + tx * 4];
            v0.x += s0.x; v0.y += s0.y; v0.z += s0.z; v0.w += s0.w;
            v1.x += s1.x; v1.y += s1.y; v1.z += s1.z; v1.w += s1.w;
        }
        *(float4*)&Cm[base + tx * 4] = v0;
        *(float4*)&Cm[base + 64 + tx * 4] = v1;
    }
}

// ---------------- RoPE (in place, q/k layout [B,T,H,HD]) ----------------
__global__ void rope_k(float* __restrict__ x, const float* __restrict__ cosb,
                       const float* __restrict__ sinb) {
    int id = blockIdx.x * 256 + threadIdx.x;     // over BT_*1024 pairs
    int m = id >> 10;
    int pi = id & 1023;
    int h = pi >> 6, dp = pi & 63;
    int t = m & (T_ - 1);
    size_t base = (size_t)m * C_ + h * HD_ + 2 * dp;
    float xr = x[base], xi = x[base + 1];
    float cc = cosb[t * 64 + dp], ss = sinb[t * 64 + dp];
    x[base]     = xr * cc - xi * ss;
    x[base + 1] = xr * ss + xi * cc;
}

// ---------------- causal flash attention (fp32) ----------------
// grid (64 bh, 16 qtiles), 256 threads, 64-query x 64-key tiles, HD=128
#define ATT_LDQ 132
#define ATT_LDP 68
#define ATT_SMEM ((2 * 64 * ATT_LDQ + 64 * ATT_LDP) * 4)
__global__ __launch_bounds__(256) void attn_k(
    const float* __restrict__ q, const float* __restrict__ kmat,
    const float* __restrict__ v, float* __restrict__ y)
{
    extern __shared__ float sm[];
    float* Qs = sm;                       // 64 x 132
    float* Ks = sm + 64 * ATT_LDQ;        // 64 x 132 (K, then reused for V)
    float* Ps = sm + 2 * 64 * ATT_LDQ;    // 64 x 68

    int bh = blockIdx.x, qt = blockIdx.y;
    int b = bh >> 4, h = bh & 15;
    int tid = threadIdx.x, r = tid >> 2, g = tid & 3;
    const float sc = 0.08838834764831845f;  // 1/sqrt(128)

    size_t qbase = ((size_t)(b * T_ + qt * 64)) * C_ + h * HD_;
    for (int i = tid; i < 64 * 32; i += 256) {
        int row = i >> 5, d4 = (i & 31) << 2;
        float4 val = *(const float4*)(q + qbase + (size_t)row * C_ + d4);
        val.x *= sc; val.y *= sc; val.z *= sc; val.w *= sc;
        *(float4*)&Qs[row * ATT_LDQ + d4] = val;
    }

    float m_run = -INFINITY, l_run = 0.f;
    float acc[32];
#pragma unroll
    for (int j = 0; j < 32; j++) acc[j] = 0.f;

    int qg = qt * 64 + r;
    for (int kt = 0; kt <= qt; kt++) {
        __syncthreads();   // previous V reads done; also guards Qs on first iter boundary
        size_t kbase = ((size_t)(b * T_ + kt * 64)) * C_ + h * HD_;
        for (int i = tid; i < 64 * 32; i += 256) {
            int row = i >> 5, d4 = (i & 31) << 2;
            *(float4*)&Ks[row * ATT_LDQ + d4] =
                *(const float4*)(kmat + kbase + (size_t)row * C_ + d4);
        }
        __syncthreads();

        float s[16];
#pragma unroll
        for (int j = 0; j < 16; j++) s[j] = 0.f;
        const float* qrow = &Qs[r * ATT_LDQ];
#pragma unroll 8
        for (int d = 0; d < 128; d++) {
            float qv = qrow[d];
#pragma unroll
            for (int j = 0; j < 16; j++)
                s[j] = fmaf(qv, Ks[(g + 4 * j) * ATT_LDQ + d], s[j]);
        }
        if (kt == qt) {
#pragma unroll
            for (int j = 0; j < 16; j++) {
                int kg = kt * 64 + g + 4 * j;
                if (kg > qg) s[j] = -1e30f;
            }
        }
        float tmax = s[0];
#pragma unroll
        for (int j = 1; j < 16; j++) tmax = fmaxf(tmax, s[j]);
        tmax = fmaxf(tmax, __shfl_xor_sync(0xffffffffu, tmax, 1));
        tmax = fmaxf(tmax, __shfl_xor_sync(0xffffffffu, tmax, 2));
        float m_new = fmaxf(m_run, tmax);
        float alpha = expf(m_run - m_new);
        float psum = 0.f;
#pragma unroll
        for (int j = 0; j < 16; j++) {
            float p = expf(s[j] - m_new);
            Ps[r * ATT_LDP + g + 4 * j] = p;
            psum += p;
        }
        psum += __shfl_xor_sync(0xffffffffu, psum, 1);
        psum += __shfl_xor_sync(0xffffffffu, psum, 2);
        l_run = l_run * alpha + psum;
        m_run = m_new;
#pragma unroll
        for (int j = 0; j < 32; j++) acc[j] *= alpha;

        __syncthreads();   // done reading K, OK to overwrite with V
        for (int i = tid; i < 64 * 32; i += 256) {
            int row = i >> 5, d4 = (i & 31) << 2;
            *(float4*)&Ks[row * ATT_LDQ + d4] =
                *(const float4*)(v + kbase + (size_t)row * C_ + d4);
        }
        __syncthreads();
#pragma unroll 4
        for (int kk = 0; kk < 64; kk++) {
            float p = Ps[r * ATT_LDP + kk];
            const float* vrow = &Ks[kk * ATT_LDQ];
#pragma unroll
            for (int j = 0; j < 32; j++)
                acc[j] = fmaf(p, vrow[g + 4 * j], acc[j]);
        }
    }

    float invl = 1.f / l_run;
#pragma unroll
    for (int j = 0; j < 32; j++)
        y[qbase + (size_t)r * C_ + g + 4 * j] = acc[j] * invl;
}

// ---------------- silu(gate)*up ----------------
__global__ void siluprod_k(const float* __restrict__ g, const float* __restrict__ u,
                           float* __restrict__ p) {
    size_t id = (size_t)blockIdx.x * 256 + threadIdx.x;
    float gv = g[id];
    float s = gv / (1.f + expf(-gv));
    p[id] = s * u[id];
}

// ---------------- launch ----------------
extern "C" void kernel_launch(void* const* d_in, const int* in_sizes, int n_in,
                              void* d_out, int out_size) {
    const float* x   = (const float*)d_in[0];
    const float* fc  = (const float*)d_in[1];
    const float* fs  = (const float*)d_in[2];
    const float* anw = (const float*)d_in[3];
    const float* fnw = (const float*)d_in[4];
    const float* wq  = (const float*)d_in[5];
    const float* wk  = (const float*)d_in[6];
    const float* wv  = (const float*)d_in[7];
    const float* wo  = (const float*)d_in[8];
    const float* wg  = (const float*)d_in[9];
    const float* wu  = (const float*)d_in[10];
    const float* wd  = (const float*)d_in[11];
    float* out = (float*)d_out;

    float *Wq, *Wk, *Wv, *Wo, *Wg, *Wu, *Wd;
    float *XN, *Q, *K, *V, *Y, *Hb, *HN, *GATE, *UP, *PROD, *SC;
    cudaGetSymbolAddress((void**)&Wq, g_Wq);
    cudaGetSymbolAddress((void**)&Wk, g_Wk);
    cudaGetSymbolAddress((void**)&Wv, g_Wv);
    cudaGetSymbolAddress((void**)&Wo, g_Wo);
    cudaGetSymbolAddress((void**)&Wg, g_Wg);
    cudaGetSymbolAddress((void**)&Wu, g_Wu);
    cudaGetSymbolAddress((void**)&Wd, g_Wd);
    cudaGetSymbolAddress((void**)&XN, g_xn);
    cudaGetSymbolAddress((void**)&Q,  g_q);
    cudaGetSymbolAddress((void**)&K,  g_kk);
    cudaGetSymbolAddress((void**)&V,  g_v);
    cudaGetSymbolAddress((void**)&Y,  g_y);
    cudaGetSymbolAddress((void**)&Hb, g_h);
    cudaGetSymbolAddress((void**)&HN, g_hn);
    cudaGetSymbolAddress((void**)&GATE, g_gate);
    cudaGetSymbolAddress((void**)&UP, g_up);
    cudaGetSymbolAddress((void**)&PROD, g_prod);
    cudaGetSymbolAddress((void**)&SC, g_scale);

    cudaFuncSetAttribute(attn_k, cudaFuncAttributeMaxDynamicSharedMemorySize, ATT_SMEM);

    build_tables_k<<<1, 1>>>();
    compute_scales_k<<<8, 256>>>(wq, 256 * 256, SC + 0);
    compute_scales_k<<<8, 256>>>(wk, 256 * 256, SC + 8);
    compute_scales_k<<<8, 256>>>(wv, 256 * 256, SC + 16);
    compute_scales_k<<<8, 256>>>(wo, 256 * 256, SC + 24);
    compute_scales_k<<<8, 256>>>(wg, 683 * 256, SC + 32);
    compute_scales_k<<<8, 256>>>(wu, 683 * 256, SC + 40);
    compute_scales_k<<<8, 256>>>(wd, 256 * 683, SC + 48);

    build_full_sq_k<<<(C_ * C_) / 256, 256>>>(wq, SC + 0,  Wq);
    build_full_sq_k<<<(C_ * C_) / 256, 256>>>(wk, SC + 8,  Wk);
    build_full_sq_k<<<(C_ * C_) / 256, 256>>>(wv, SC + 16, Wv);
    build_full_sq_k<<<(C_ * C_) / 256, 256>>>(wo, SC + 24, Wo);
    build_full_h_k<<<(HIDP_ * C_) / 256, 256>>>(wg, SC + 32, Wg);
    build_full_h_k<<<(HIDP_ * C_) / 256, 256>>>(wu, SC + 40, Wu);
    build_full_d_k<<<(C_ * HIDP_) / 256, 256>>>(wd, SC + 48, Wd);

    rmsnorm_k<<<BT_, 256>>>(x, anw, XN);

    dim3 gsq(C_ / 128, BT_ / 128);
    gemm_k<<<gsq, 256>>>(XN, Wq, nullptr, Q, BT_, C_, C_);
    gemm_k<<<gsq, 256>>>(XN, Wk, nullptr, K, BT_, C_, C_);
    gemm_k<<<gsq, 256>>>(XN, Wv, nullptr, V, BT_, C_, C_);

    rope_k<<<(BT_ * 1024) / 256, 256>>>(Q, fc, fs);
    rope_k<<<(BT_ * 1024) / 256, 256>>>(K, fc, fs);

    attn_k<<<dim3(64, 16), 256, ATT_SMEM>>>(Q, K, V, Y);

    gemm_k<<<gsq, 256>>>(Y, Wo, x, Hb, BT_, C_, C_);
    rmsnorm_k<<<BT_, 256>>>(Hb, fnw, HN);

    dim3 gh(HIDP_ / 128, BT_ / 128);
    gemm_k<<<gh, 256>>>(HN, Wg, nullptr, GATE, BT_, HIDP_, C_);
    gemm_k<<<gh, 256>>>(HN, Wu, nullptr, UP, BT_, HIDP_, C_);

    siluprod_k<<<(int)(((size_t)BT_ * HIDP_) / 256), 256>>>(GATE, UP, PROD);

    gemm_k<<<gsq, 256>>>(PROD, Wd, Hb, out, BT_, C_, HIDP_);
}

// round 4
// speedup vs baseline: 2.0068x; 2.0068x over previous
#include <cuda_runtime.h>
#include <cuda_bf16.h>
#include <math.h>
#include <stdint.h>

// ---------------- problem constants ----------------
#define BT_   4096          // B*T
#define C_    2048
#define T_    1024
#define H_    16
#define HD_   128
#define HID_  5464
#define HIDP_ 5504          // padded hidden (43*128)

// ---------------- helpers ----------------
__device__ __forceinline__ uint32_t smem_u32(const void* p) {
    uint32_t a;
    asm("{ .reg .u64 t; cvta.to.shared.u64 t, %1; cvt.u32.u64 %0, t; }" : "=r"(a) : "l"(p));
    return a;
}
#define SW128(o) ((o) ^ (((o) >> 3) & 0x70))

__device__ __forceinline__ void cp16(uint32_t s, const void* g) {
    asm volatile("cp.async.cg.shared.global [%0], [%1], 16;"
                 :: "r"(s), "l"(__cvta_generic_to_global(g)));
}
__device__ __forceinline__ void ldm_x4(uint32_t addr, uint32_t& r0, uint32_t& r1,
                                       uint32_t& r2, uint32_t& r3) {
    asm volatile("ldmatrix.sync.aligned.m8n8.x4.shared.b16 {%0,%1,%2,%3}, [%4];"
                 : "=r"(r0), "=r"(r1), "=r"(r2), "=r"(r3) : "r"(addr));
}
__device__ __forceinline__ void mma16816(float* c, const uint32_t* a, uint32_t b0, uint32_t b1) {
    asm volatile(
        "mma.sync.aligned.m16n8k16.row.col.f32.bf16.bf16.f32 "
        "{%0,%1,%2,%3}, {%4,%5,%6,%7}, {%8,%9}, {%0,%1,%2,%3};"
        : "+f"(c[0]), "+f"(c[1]), "+f"(c[2]), "+f"(c[3])
        : "r"(a[0]), "r"(a[1]), "r"(a[2]), "r"(a[3]), "r"(b0), "r"(b1));
}

// ---------------- scratch (device globals, no allocs) ----------------
__device__ __nv_bfloat16 g_Wqh[C_*C_],  g_Wql[C_*C_];
__device__ __nv_bfloat16 g_Wkh[C_*C_],  g_Wkl[C_*C_];
__device__ __nv_bfloat16 g_Wvh[C_*C_],  g_Wvl[C_*C_];
__device__ __nv_bfloat16 g_Woh[C_*C_],  g_Wol[C_*C_];
__device__ __nv_bfloat16 g_Wgh[HIDP_*C_], g_Wgl[HIDP_*C_];
__device__ __nv_bfloat16 g_Wuh[HIDP_*C_], g_Wul[HIDP_*C_];
__device__ __nv_bfloat16 g_Wdh[C_*HIDP_], g_Wdl[C_*HIDP_];
__device__ __nv_bfloat16 g_XNh[BT_*C_],  g_XNl[BT_*C_];
__device__ __nv_bfloat16 g_Yh [BT_*C_],  g_Yl [BT_*C_];
__device__ __nv_bfloat16 g_HNh[BT_*C_],  g_HNl[BT_*C_];
__device__ __nv_bfloat16 g_PRh[(size_t)BT_*HIDP_], g_PRl[(size_t)BT_*HIDP_];
__device__ float g_q [BT_*C_];
__device__ float g_kk[BT_*C_];
__device__ float g_v [BT_*C_];
__device__ float g_h [BT_*C_];
__device__ float g_gate[(size_t)BT_*HIDP_];
__device__ float g_up  [(size_t)BT_*HIDP_];
__device__ int    g_Ji[64];
__device__ float  g_Sg[64];
__device__ float  g_scale[56];
__device__ double g_part[64];

// ---------------- octonion table ----------------
__global__ void build_tables_k() {
    int idx[8][8]; float sg[8][8];
    for (int j = 0; j < 8; j++) { idx[0][j] = j; sg[0][j] = 1.f; }
    for (int i = 1; i < 8; i++) {
        idx[i][0] = i; sg[i][0] = 1.f;
        idx[i][i] = 0; sg[i][i] = -1.f;
    }
    const int tr[7][3] = {{1,2,3},{1,4,5},{1,7,6},{2,4,6},{2,5,7},{3,4,7},{3,6,5}};
    for (int t = 0; t < 7; t++) {
        int a = tr[t][0], b = tr[t][1], c = tr[t][2];
        int per[3][3] = {{a,b,c},{b,c,a},{c,a,b}};
        for (int u = 0; u < 3; u++) {
            int p = per[u][0], q = per[u][1], r = per[u][2];
            idx[p][q] = r; sg[p][q] = 1.f;
            idx[q][p] = r; sg[q][p] = -1.f;
        }
    }
    for (int i = 0; i < 8; i++)
        for (int j = 0; j < 8; j++) {
            int k = idx[i][j];
            g_Ji[k*8 + j] = i;
            g_Sg[k*8 + j] = sg[i][j];
        }
}

// ---------------- scales: mean(|W|) per slab, 8x8 parallel ----------------
__global__ void scales_part_k(const float* __restrict__ W, int OP, double* __restrict__ part) {
    int i = blockIdx.x, sl = blockIdx.y;
    const float* Wi = W + (size_t)i * OP;
    int per = (OP + 7) / 8;
    int st = sl * per, en = min(OP, st + per);
    double s = 0.0;
    for (int t = st + threadIdx.x; t < en; t += 256) s += (double)fabsf(Wi[t]);
    __shared__ double red[256];
    red[threadIdx.x] = s; __syncthreads();
    for (int stp = 128; stp > 0; stp >>= 1) {
        if (threadIdx.x < stp) red[threadIdx.x] += red[threadIdx.x + stp];
        __syncthreads();
    }
    if (threadIdx.x == 0) part[i*8 + sl] = red[0];
}
__global__ void scales_fin_k(const double* __restrict__ part, int OP, float* __restrict__ out) {
    int i = threadIdx.x;
    double s = 0.0;
    for (int j = 0; j < 8; j++) s += part[i*8 + j];
    out[i] = (float)(s / (double)OP);
}

__device__ __forceinline__ float tquant(float w, float s) {
    float q = rintf(w / (s + 1e-8f));
    q = fmaxf(-1.f, fminf(1.f, q));
    return q * s;
}
__device__ __forceinline__ void split_store(float v, __nv_bfloat16* ph, __nv_bfloat16* pl) {
    __nv_bfloat16 h = __float2bfloat16(v);
    *ph = h;
    *pl = __float2bfloat16(v - __bfloat162float(h));
}

// ---------------- weight build (hi/lo bf16) ----------------
__global__ void build_full_sq_k(const float* __restrict__ W, const float* __restrict__ sc,
                                __nv_bfloat16* __restrict__ Fh, __nv_bfloat16* __restrict__ Fl) {
    int id = blockIdx.x * 256 + threadIdx.x;
    int r = id >> 11, c = id & 2047;
    int kb = r >> 8, o = r & 255, jb = c >> 8, p = c & 255;
    int i = g_Ji[kb*8 + jb];
    float w = W[((size_t)i << 16) + (o << 8) + p];
    float v = g_Sg[kb*8 + jb] * tquant(w, sc[i]);
    split_store(v, Fh + id, Fl + id);
}
__global__ void build_full_h_k(const float* __restrict__ W, const float* __restrict__ sc,
                               __nv_bfloat16* __restrict__ Fh, __nv_bfloat16* __restrict__ Fl) {
    int id = blockIdx.x * 256 + threadIdx.x;
    int r = id >> 11, c = id & 2047;
    if (r >= HID_) { Fh[id] = __float2bfloat16(0.f); Fl[id] = __float2bfloat16(0.f); return; }
    int kb = r / 683, o = r - kb * 683;
    int jb = c >> 8, p = c & 255;
    int i = g_Ji[kb*8 + jb];
    float w = W[((size_t)i * 683 + o) * 256 + p];
    float v = g_Sg[kb*8 + jb] * tquant(w, sc[i]);
    split_store(v, Fh + id, Fl + id);
}
__global__ void build_full_d_k(const float* __restrict__ W, const float* __restrict__ sc,
                               __nv_bfloat16* __restrict__ Fh, __nv_bfloat16* __restrict__ Fl) {
    int id = blockIdx.x * 256 + threadIdx.x;
    int r = id / HIDP_, c = id - r * HIDP_;
    if (c >= HID_) { Fh[id] = __float2bfloat16(0.f); Fl[id] = __float2bfloat16(0.f); return; }
    int kb = r >> 8, o = r & 255;
    int jb = c / 683, p = c - jb * 683;
    int i = g_Ji[kb*8 + jb];
    float w = W[((size_t)i * 256 + o) * 683 + p];
    float v = g_Sg[kb*8 + jb] * tquant(w, sc[i]);
    split_store(v, Fh + id, Fl + id);
}

// ---------------- rmsnorm -> bf16 hi/lo ----------------
__global__ void rmsnorm_k(const float* __restrict__ x, const float* __restrict__ w,
                          __nv_bfloat16* __restrict__ oh, __nv_bfloat16* __restrict__ ol) {
    int row = blockIdx.x;
    const float* xr = x + (size_t)row * C_;
    float s = 0.f;
    for (int c = threadIdx.x; c < C_; c += 256) { float v = xr[c]; s += v * v; }
    __shared__ float red[256];
    red[threadIdx.x] = s; __syncthreads();
    for (int st = 128; st > 0; st >>= 1) {
        if (threadIdx.x < st) red[threadIdx.x] += red[threadIdx.x + st];
        __syncthreads();
    }
    float inv = 1.0f / sqrtf(red[0] / (float)C_ + 1e-6f);
    for (int c = threadIdx.x; c < C_; c += 256) {
        float v = xr[c] * inv * w[c];
        split_store(v, oh + (size_t)row * C_ + c, ol + (size_t)row * C_ + c);
    }
}

// ---------------- mma.sync GEMM ----------------
// C[M,N] = Ahi@Bhi^T + Alo@Bhi^T + Ahi@Blo^T (+addsrc)
// A: [M,K] bf16 row-major (hi,lo); B: [N,K] bf16 row-major (hi,lo). K%64==0.
// CTA tile 128x128, BK=64, 8 warps (4x2), warp tile 32x64 of m16n8k16.
#define G_ABYTES (128*64*2)               // 16KB
#define G_STAGE  (2*G_ABYTES)             // 32KB (A then B)
#define GSMEM_TOTAL (2*G_STAGE)           // 64KB, two stages

__global__ __launch_bounds__(256) void gemm_mma_k(
    const __nv_bfloat16* __restrict__ Ah, const __nv_bfloat16* __restrict__ Al,
    const __nv_bfloat16* __restrict__ Bh, const __nv_bfloat16* __restrict__ Bl,
    const float* __restrict__ addsrc, float* __restrict__ Cm,
    int M, int N, int K)
{
    extern __shared__ __align__(1024) char smem[];
    int tid = threadIdx.x, wid = tid >> 5, lane = tid & 31;
    int wr = wid >> 1, wc = wid & 1;
    int bm = blockIdx.y * 128, bn = blockIdx.x * 128;
    uint32_t sbase = smem_u32(smem);

    const __nv_bfloat16* As[3] = {Ah, Al, Ah};
    const __nv_bfloat16* Bs[3] = {Bh, Bh, Bl};
    int nk = K >> 6, total = 3 * nk;

    float acc[2][8][4];
#pragma unroll
    for (int mt = 0; mt < 2; mt++)
#pragma unroll
        for (int nt = 0; nt < 8; nt++)
#pragma unroll
            for (int e = 0; e < 4; e++) acc[mt][nt][e] = 0.f;

    // ldmatrix lane-address components
    int a_row = ((lane >> 3) & 1) * 8 + (lane & 7);   // row within m16
    int a_kb  = (lane >> 4) * 16;                     // byte offset within k16 (16B halves)
    int b_n   = ((lane >> 4) & 1) * 8 + (lane & 7);   // row within n16
    int b_kb  = ((lane >> 3) & 1) * 16;

#define ISSUE(ch) do {                                                        \
        int t_ = (ch) >= 2*nk ? 2 : ((ch) >= nk ? 1 : 0);                     \
        int k0_ = ((ch) - t_*nk) << 6;                                        \
        uint32_t sA_ = sbase + ((ch) & 1) * G_STAGE;                          \
        uint32_t sB_ = sA_ + G_ABYTES;                                        \
        const __nv_bfloat16* Ap_ = As[t_];                                    \
        const __nv_bfloat16* Bp_ = Bs[t_];                                    \
        _Pragma("unroll")                                                     \
        for (int u = 0; u < 4; u++) {                                         \
            int i_ = tid + u * 256;                                           \
            int row_ = i_ >> 3, seg_ = i_ & 7;                                \
            cp16(sA_ + SW128(row_ * 128 + seg_ * 16),                         \
                 Ap_ + (size_t)(bm + row_) * K + k0_ + seg_ * 8);             \
            cp16(sB_ + SW128(row_ * 128 + seg_ * 16),                         \
                 Bp_ + (size_t)(bn + row_) * K + k0_ + seg_ * 8);             \
        }                                                                     \
        asm volatile("cp.async.commit_group;" ::: "memory");                  \
    } while (0)

    ISSUE(0);
    for (int ch = 0; ch < total; ch++) {
        if (ch + 1 < total) {
            ISSUE(ch + 1);
            asm volatile("cp.async.wait_group 1;" ::: "memory");
        } else {
            asm volatile("cp.async.wait_group 0;" ::: "memory");
        }
        __syncthreads();

        uint32_t sA = sbase + (ch & 1) * G_STAGE;
        uint32_t sB = sA + G_ABYTES;
#pragma unroll
        for (int kk = 0; kk < 4; kk++) {
            uint32_t a[2][4];
#pragma unroll
            for (int mt = 0; mt < 2; mt++) {
                uint32_t byte = (uint32_t)(wr * 32 + mt * 16 + a_row) * 128 + kk * 32 + a_kb;
                ldm_x4(sA + SW128(byte), a[mt][0], a[mt][1], a[mt][2], a[mt][3]);
            }
            uint32_t b[4][4];
#pragma unroll
            for (int np = 0; np < 4; np++) {
                uint32_t byte = (uint32_t)(wc * 64 + np * 16 + b_n) * 128 + kk * 32 + b_kb;
                ldm_x4(sB + SW128(byte), b[np][0], b[np][1], b[np][2], b[np][3]);
            }
#pragma unroll
            for (int mt = 0; mt < 2; mt++)
#pragma unroll
                for (int nt = 0; nt < 8; nt++)
                    mma16816(acc[mt][nt], a[mt], b[nt >> 1][(nt & 1) * 2],
                             b[nt >> 1][(nt & 1) * 2 + 1]);
        }
        __syncthreads();
    }

    // epilogue: direct stores (+ optional residual)
#pragma unroll
    for (int mt = 0; mt < 2; mt++)
#pragma unroll
        for (int nt = 0; nt < 8; nt++) {
            int r0 = bm + wr * 32 + mt * 16 + (lane >> 2);
            int c  = bn + wc * 64 + nt * 8 + (lane & 3) * 2;
            size_t i0 = (size_t)r0 * N + c;
            size_t i1 = i0 + (size_t)8 * N;
            float2 v0 = make_float2(acc[mt][nt][0], acc[mt][nt][1]);
            float2 v1 = make_float2(acc[mt][nt][2], acc[mt][nt][3]);
            if (addsrc) {
                float2 s0 = *(const float2*)&addsrc[i0];
                float2 s1 = *(const float2*)&addsrc[i1];
                v0.x += s0.x; v0.y += s0.y;
                v1.x += s1.x; v1.y += s1.y;
            }
            *(float2*)&Cm[i0] = v0;
            *(float2*)&Cm[i1] = v1;
        }
}

// ---------------- RoPE ----------------
__global__ void rope_k(float* __restrict__ x, const float* __restrict__ cosb,
                       const float* __restrict__ sinb) {
    int id = blockIdx.x * 256 + threadIdx.x;
    int m = id >> 10;
    int pi = id & 1023;
    int h = pi >> 6, dp = pi & 63;
    int t = m & (T_ - 1);
    size_t base = (size_t)m * C_ + h * HD_ + 2 * dp;
    float xr = x[base], xi = x[base + 1];
    float cc = cosb[t * 64 + dp], ss = sinb[t * 64 + dp];
    x[base]     = xr * cc - xi * ss;
    x[base + 1] = xr * ss + xi * cc;
}

// ---------------- causal flash attention (fp32), writes bf16 hi/lo ----------------
#define ATT_LDQ 132
#define ATT_LDP 68
#define ATT_SMEM ((2 * 64 * ATT_LDQ + 64 * ATT_LDP) * 4)
__global__ __launch_bounds__(256) void attn_k(
    const float* __restrict__ q, const float* __restrict__ kmat,
    const float* __restrict__ v,
    __nv_bfloat16* __restrict__ yh, __nv_bfloat16* __restrict__ yl)
{
    extern __shared__ float sm[];
    float* Qs = sm;
    float* Ks = sm + 64 * ATT_LDQ;
    float* Ps = sm + 2 * 64 * ATT_LDQ;

    int bh = blockIdx.x, qt = blockIdx.y;
    int b = bh >> 4, h = bh & 15;
    int tid = threadIdx.x, r = tid >> 2, g = tid & 3;
    const float sc = 0.08838834764831845f;

    size_t qbase = ((size_t)(b * T_ + qt * 64)) * C_ + h * HD_;
    for (int i = tid; i < 64 * 32; i += 256) {
        int row = i >> 5, d4 = (i & 31) << 2;
        float4 val = *(const float4*)(q + qbase + (size_t)row * C_ + d4);
        val.x *= sc; val.y *= sc; val.z *= sc; val.w *= sc;
        *(float4*)&Qs[row * ATT_LDQ + d4] = val;
    }

    float m_run = -INFINITY, l_run = 0.f;
    float acc[32];
#pragma unroll
    for (int j = 0; j < 32; j++) acc[j] = 0.f;

    int qg = qt * 64 + r;
    for (int kt = 0; kt <= qt; kt++) {
        __syncthreads();
        size_t kbase = ((size_t)(b * T_ + kt * 64)) * C_ + h * HD_;
        for (int i = tid; i < 64 * 32; i += 256) {
            int row = i >> 5, d4 = (i & 31) << 2;
            *(float4*)&Ks[row * ATT_LDQ + d4] =
                *(const float4*)(kmat + kbase + (size_t)row * C_ + d4);
        }
        __syncthreads();

        float s[16];
#pragma unroll
        for (int j = 0; j < 16; j++) s[j] = 0.f;
        const float* qrow = &Qs[r * ATT_LDQ];
#pragma unroll 8
        for (int d = 0; d < 128; d++) {
            float qv = qrow[d];
#pragma unroll
            for (int j = 0; j < 16; j++)
                s[j] = fmaf(qv, Ks[(g + 4 * j) * ATT_LDQ + d], s[j]);
        }
        if (kt == qt) {
#pragma unroll
            for (int j = 0; j < 16; j++) {
                int kg = kt * 64 + g + 4 * j;
                if (kg > qg) s[j] = -1e30f;
            }
        }
        float tmax = s[0];
#pragma unroll
        for (int j = 1; j < 16; j++) tmax = fmaxf(tmax, s[j]);
        tmax = fmaxf(tmax, __shfl_xor_sync(0xffffffffu, tmax, 1));
        tmax = fmaxf(tmax, __shfl_xor_sync(0xffffffffu, tmax, 2));
        float m_new = fmaxf(m_run, tmax);
        float alpha = expf(m_run - m_new);
        float psum = 0.f;
#pragma unroll
        for (int j = 0; j < 16; j++) {
            float p = expf(s[j] - m_new);
            Ps[r * ATT_LDP + g + 4 * j] = p;
            psum += p;
        }
        psum += __shfl_xor_sync(0xffffffffu, psum, 1);
        psum += __shfl_xor_sync(0xffffffffu, psum, 2);
        l_run = l_run * alpha + psum;
        m_run = m_new;
#pragma unroll
        for (int j = 0; j < 32; j++) acc[j] *= alpha;

        __syncthreads();
        for (int i = tid; i < 64 * 32; i += 256) {
            int row = i >> 5, d4 = (i & 31) << 2;
            *(float4*)&Ks[row * ATT_LDQ + d4] =
                *(const float4*)(v + kbase + (size_t)row * C_ + d4);
        }
        __syncthreads();
#pragma unroll 4
        for (int kk = 0; kk < 64; kk++) {
            float p = Ps[r * ATT_LDP + kk];
            const float* vrow = &Ks[kk * ATT_LDQ];
#pragma unroll
            for (int j = 0; j < 32; j++)
                acc[j] = fmaf(p, vrow[g + 4 * j], acc[j]);
        }
    }

    float invl = 1.f / l_run;
#pragma unroll
    for (int j = 0; j < 32; j++) {
        float val = acc[j] * invl;
        size_t o = qbase + (size_t)r * C_ + g + 4 * j;
        split_store(val, yh + o, yl + o);
    }
}

// ---------------- silu(gate)*up -> bf16 hi/lo ----------------
__global__ void siluprod_k(const float* __restrict__ g, const float* __restrict__ u,
                           __nv_bfloat16* __restrict__ ph, __nv_bfloat16* __restrict__ pl) {
    size_t id = (size_t)blockIdx.x * 256 + threadIdx.x;
    float gv = g[id];
    float s = gv / (1.f + expf(-gv));
    split_store(s * u[id], ph + id, pl + id);
}

// ---------------- launch ----------------
extern "C" void kernel_launch(void* const* d_in, const int* in_sizes, int n_in,
                              void* d_out, int out_size) {
    const float* x   = (const float*)d_in[0];
    const float* fc  = (const float*)d_in[1];
    const float* fs  = (const float*)d_in[2];
    const float* anw = (const float*)d_in[3];
    const float* fnw = (const float*)d_in[4];
    const float* wq  = (const float*)d_in[5];
    const float* wk  = (const float*)d_in[6];
    const float* wv  = (const float*)d_in[7];
    const float* wo  = (const float*)d_in[8];
    const float* wg  = (const float*)d_in[9];
    const float* wu  = (const float*)d_in[10];
    const float* wd  = (const float*)d_in[11];
    float* out = (float*)d_out;

    __nv_bfloat16 *Wqh,*Wql,*Wkh,*Wkl,*Wvh,*Wvl,*Woh,*Wol,*Wgh,*Wgl,*Wuh,*Wul,*Wdh,*Wdl;
    __nv_bfloat16 *XNh,*XNl,*Yh,*Yl,*HNh,*HNl,*PRh,*PRl;
    float *Q,*K,*V,*Hb,*GATE,*UP,*SC;
    double* PART;
    cudaGetSymbolAddress((void**)&Wqh, g_Wqh); cudaGetSymbolAddress((void**)&Wql, g_Wql);
    cudaGetSymbolAddress((void**)&Wkh, g_Wkh); cudaGetSymbolAddress((void**)&Wkl, g_Wkl);
    cudaGetSymbolAddress((void**)&Wvh, g_Wvh); cudaGetSymbolAddress((void**)&Wvl, g_Wvl);
    cudaGetSymbolAddress((void**)&Woh, g_Woh); cudaGetSymbolAddress((void**)&Wol, g_Wol);
    cudaGetSymbolAddress((void**)&Wgh, g_Wgh); cudaGetSymbolAddress((void**)&Wgl, g_Wgl);
    cudaGetSymbolAddress((void**)&Wuh, g_Wuh); cudaGetSymbolAddress((void**)&Wul, g_Wul);
    cudaGetSymbolAddress((void**)&Wdh, g_Wdh); cudaGetSymbolAddress((void**)&Wdl, g_Wdl);
    cudaGetSymbolAddress((void**)&XNh, g_XNh); cudaGetSymbolAddress((void**)&XNl, g_XNl);
    cudaGetSymbolAddress((void**)&Yh,  g_Yh);  cudaGetSymbolAddress((void**)&Yl,  g_Yl);
    cudaGetSymbolAddress((void**)&HNh, g_HNh); cudaGetSymbolAddress((void**)&HNl, g_HNl);
    cudaGetSymbolAddress((void**)&PRh, g_PRh); cudaGetSymbolAddress((void**)&PRl, g_PRl);
    cudaGetSymbolAddress((void**)&Q,  g_q);
    cudaGetSymbolAddress((void**)&K,  g_kk);
    cudaGetSymbolAddress((void**)&V,  g_v);
    cudaGetSymbolAddress((void**)&Hb, g_h);
    cudaGetSymbolAddress((void**)&GATE, g_gate);
    cudaGetSymbolAddress((void**)&UP, g_up);
    cudaGetSymbolAddress((void**)&SC, g_scale);
    cudaGetSymbolAddress((void**)&PART, g_part);

    cudaFuncSetAttribute(attn_k, cudaFuncAttributeMaxDynamicSharedMemorySize, ATT_SMEM);
    cudaFuncSetAttribute(gemm_mma_k, cudaFuncAttributeMaxDynamicSharedMemorySize, GSMEM_TOTAL);

    build_tables_k<<<1, 1>>>();
    dim3 gsc(8, 8);
    scales_part_k<<<gsc, 256>>>(wq, 256*256, PART); scales_fin_k<<<1, 8>>>(PART, 256*256, SC + 0);
    scales_part_k<<<gsc, 256>>>(wk, 256*256, PART); scales_fin_k<<<1, 8>>>(PART, 256*256, SC + 8);
    scales_part_k<<<gsc, 256>>>(wv, 256*256, PART); scales_fin_k<<<1, 8>>>(PART, 256*256, SC + 16);
    scales_part_k<<<gsc, 256>>>(wo, 256*256, PART); scales_fin_k<<<1, 8>>>(PART, 256*256, SC + 24);
    scales_part_k<<<gsc, 256>>>(wg, 683*256, PART); scales_fin_k<<<1, 8>>>(PART, 683*256, SC + 32);
    scales_part_k<<<gsc, 256>>>(wu, 683*256, PART); scales_fin_k<<<1, 8>>>(PART, 683*256, SC + 40);
    scales_part_k<<<gsc, 256>>>(wd, 256*683, PART); scales_fin_k<<<1, 8>>>(PART, 256*683, SC + 48);

    build_full_sq_k<<<(C_ * C_) / 256, 256>>>(wq, SC + 0,  Wqh, Wql);
    build_full_sq_k<<<(C_ * C_) / 256, 256>>>(wk, SC + 8,  Wkh, Wkl);
    build_full_sq_k<<<(C_ * C_) / 256, 256>>>(wv, SC + 16, Wvh, Wvl);
    build_full_sq_k<<<(C_ * C_) / 256, 256>>>(wo, SC + 24, Woh, Wol);
    build_full_h_k<<<(HIDP_ * C_) / 256, 256>>>(wg, SC + 32, Wgh, Wgl);
    build_full_h_k<<<(HIDP_ * C_) / 256, 256>>>(wu, SC + 40, Wuh, Wul);
    build_full_d_k<<<(C_ * HIDP_) / 256, 256>>>(wd, SC + 48, Wdh, Wdl);

    rmsnorm_k<<<BT_, 256>>>(x, anw, XNh, XNl);

    dim3 gsq(C_ / 128, BT_ / 128);
    gemm_mma_k<<<gsq, 256, GSMEM_TOTAL>>>(XNh, XNl, Wqh, Wql, nullptr, Q, BT_, C_, C_);
    gemm_mma_k<<<gsq, 256, GSMEM_TOTAL>>>(XNh, XNl, Wkh, Wkl, nullptr, K, BT_, C_, C_);
    gemm_mma_k<<<gsq, 256, GSMEM_TOTAL>>>(XNh, XNl, Wvh, Wvl, nullptr, V, BT_, C_, C_);

    rope_k<<<(BT_ * 1024) / 256, 256>>>(Q, fc, fs);
    rope_k<<<(BT_ * 1024) / 256, 256>>>(K, fc, fs);

    attn_k<<<dim3(64, 16), 256, ATT_SMEM>>>(Q, K, V, Yh, Yl);

    gemm_mma_k<<<gsq, 256, GSMEM_TOTAL>>>(Yh, Yl, Woh, Wol, x, Hb, BT_, C_, C_);
    rmsnorm_k<<<BT_, 256>>>(Hb, fnw, HNh, HNl);

    dim3 gh(HIDP_ / 128, BT_ / 128);
    gemm_mma_k<<<gh, 256, GSMEM_TOTAL>>>(HNh, HNl, Wgh, Wgl, nullptr, GATE, BT_, HIDP_, C_);
    gemm_mma_k<<<gh, 256, GSMEM_TOTAL>>>(HNh, HNl, Wuh, Wul, nullptr, UP, BT_, HIDP_, C_);

    siluprod_k<<<(int)(((size_t)BT_ * HIDP_) / 256), 256>>>(GATE, UP, PRh, PRl);

    gemm_mma_k<<<gsq, 256, GSMEM_TOTAL>>>(PRh, PRl, Wdh, Wdl, Hb, out, BT_, C_, HIDP_);
}

// round 5
// speedup vs baseline: 2.6440x; 1.3176x over previous
#include <cuda_runtime.h>
#include <cuda_bf16.h>
#include <math.h>
#include <stdint.h>

// ---------------- problem constants ----------------
#define BT_    4096          // B*T
#define C_     2048
#define T_     1024
#define H_     16
#define HD_    128
#define HID_   5464
#define HBLK_  768           // padded hidden block (6x128, 12x64)
#define HIDP2_ 6144          // 8 * 768

// ---------------- helpers ----------------
__device__ __forceinline__ uint32_t smem_u32(const void* p) {
    uint32_t a;
    asm("{ .reg .u64 t; cvta.to.shared.u64 t, %1; cvt.u32.u64 %0, t; }" : "=r"(a) : "l"(p));
    return a;
}
#define SW128(o) ((o) ^ (((o) >> 3) & 0x70))

__device__ __forceinline__ void cp16(uint32_t s, const void* g) {
    asm volatile("cp.async.cg.shared.global [%0], [%1], 16;"
                 :: "r"(s), "l"(__cvta_generic_to_global(g)));
}
__device__ __forceinline__ void ldm_x4(uint32_t addr, uint32_t& r0, uint32_t& r1,
                                       uint32_t& r2, uint32_t& r3) {
    asm volatile("ldmatrix.sync.aligned.m8n8.x4.shared.b16 {%0,%1,%2,%3}, [%4];"
                 : "=r"(r0), "=r"(r1), "=r"(r2), "=r"(r3) : "r"(addr));
}
__device__ __forceinline__ void mma16816(float* c, const uint32_t* a, uint32_t b0, uint32_t b1) {
    asm volatile(
        "mma.sync.aligned.m16n8k16.row.col.f32.bf16.bf16.f32 "
        "{%0,%1,%2,%3}, {%4,%5,%6,%7}, {%8,%9}, {%0,%1,%2,%3};"
        : "+f"(c[0]), "+f"(c[1]), "+f"(c[2]), "+f"(c[3])
        : "r"(a[0]), "r"(a[1]), "r"(a[2]), "r"(a[3]), "r"(b0), "r"(b1));
}

// ---------------- scratch (device globals, no allocs) ----------------
__device__ __nv_bfloat16 g_Wq[C_*C_];        // exact ternary (sign-folded)
__device__ __nv_bfloat16 g_Wk[C_*C_];
__device__ __nv_bfloat16 g_Wv[C_*C_];
__device__ __nv_bfloat16 g_Wo[C_*C_];
__device__ __nv_bfloat16 g_Wg[HIDP2_*C_];
__device__ __nv_bfloat16 g_Wu[HIDP2_*C_];
__device__ __nv_bfloat16 g_Wd[C_*HIDP2_];
__device__ __nv_bfloat16 g_XNh[BT_*C_],  g_XNl[BT_*C_];
__device__ __nv_bfloat16 g_Yh [BT_*C_],  g_Yl [BT_*C_];
__device__ __nv_bfloat16 g_HNh[BT_*C_],  g_HNl[BT_*C_];
__device__ __nv_bfloat16 g_PRh[(size_t)BT_*HIDP2_], g_PRl[(size_t)BT_*HIDP2_];
__device__ float g_q [BT_*C_];
__device__ float g_kk[BT_*C_];
__device__ float g_v [BT_*C_];
__device__ float g_h [BT_*C_];
__device__ float g_gate[(size_t)BT_*HIDP2_];
__device__ float g_up  [(size_t)BT_*HIDP2_];
__device__ int    g_Ji[64];
__device__ float  g_Sg[64];
__device__ float  g_scale[56];
__device__ float  g_sctab[7*64];   // per-tensor [kb*8+jb] -> scale value
__device__ double g_part[64];

// ---------------- octonion table ----------------
__global__ void build_tables_k() {
    int idx[8][8]; float sg[8][8];
    for (int j = 0; j < 8; j++) { idx[0][j] = j; sg[0][j] = 1.f; }
    for (int i = 1; i < 8; i++) {
        idx[i][0] = i; sg[i][0] = 1.f;
        idx[i][i] = 0; sg[i][i] = -1.f;
    }
    const int tr[7][3] = {{1,2,3},{1,4,5},{1,7,6},{2,4,6},{2,5,7},{3,4,7},{3,6,5}};
    for (int t = 0; t < 7; t++) {
        int a = tr[t][0], b = tr[t][1], c = tr[t][2];
        int per[3][3] = {{a,b,c},{b,c,a},{c,a,b}};
        for (int u = 0; u < 3; u++) {
            int p = per[u][0], q = per[u][1], r = per[u][2];
            idx[p][q] = r; sg[p][q] = 1.f;
            idx[q][p] = r; sg[q][p] = -1.f;
        }
    }
    for (int i = 0; i < 8; i++)
        for (int j = 0; j < 8; j++) {
            int k = idx[i][j];
            g_Ji[k*8 + j] = i;
            g_Sg[k*8 + j] = sg[i][j];
        }
}

// ---------------- scales: mean(|W|) per slab ----------------
__global__ void scales_part_k(const float* __restrict__ W, int OP, double* __restrict__ part) {
    int i = blockIdx.x, sl = blockIdx.y;
    const float* Wi = W + (size_t)i * OP;
    int per = (OP + 7) / 8;
    int st = sl * per, en = min(OP, st + per);
    double s = 0.0;
    for (int t = st + threadIdx.x; t < en; t += 256) s += (double)fabsf(Wi[t]);
    __shared__ double red[256];
    red[threadIdx.x] = s; __syncthreads();
    for (int stp = 128; stp > 0; stp >>= 1) {
        if (threadIdx.x < stp) red[threadIdx.x] += red[threadIdx.x + stp];
        __syncthreads();
    }
    if (threadIdx.x == 0) part[i*8 + sl] = red[0];
}
__global__ void scales_fin_k(const double* __restrict__ part, int OP, float* __restrict__ out) {
    int i = threadIdx.x;
    double s = 0.0;
    for (int j = 0; j < 8; j++) s += part[i*8 + j];
    out[i] = (float)(s / (double)OP);
}
// sctab[t][kb*8+jb] = scale[t][ Ji[kb*8+jb] ]
__global__ void build_sctab_k() {
    int tid = threadIdx.x;            // 448 threads
    int t = tid >> 6, e = tid & 63;
    if (t < 7) g_sctab[t*64 + e] = g_scale[t*8 + g_Ji[e]];
}

__device__ __forceinline__ float tsign(float w, float s) {
    float q = rintf(w / (s + 1e-8f));
    return fmaxf(-1.f, fminf(1.f, q));      // exact -1/0/+1
}
__device__ __forceinline__ void split_store(float v, __nv_bfloat16* ph, __nv_bfloat16* pl) {
    __nv_bfloat16 h = __float2bfloat16(v);
    *ph = h;
    *pl = __float2bfloat16(v - __bfloat162float(h));
}

// ---------------- ternary weight builds (sign-folded, exact bf16) ----------------
__global__ void build_tq_sq_k(const float* __restrict__ W, const float* __restrict__ sc,
                              __nv_bfloat16* __restrict__ F) {
    int id = blockIdx.x * 256 + threadIdx.x;
    int r = id >> 11, c = id & 2047;
    int kb = r >> 8, o = r & 255, jb = c >> 8, p = c & 255;
    int i = g_Ji[kb*8 + jb];
    float w = W[((size_t)i << 16) + (o << 8) + p];
    F[id] = __float2bfloat16(g_Sg[kb*8 + jb] * tsign(w, sc[i]));
}
// gate/up: [HIDP2, C]  rows padded per 768-block (683 valid)
__global__ void build_tq_h_k(const float* __restrict__ W, const float* __restrict__ sc,
                             __nv_bfloat16* __restrict__ F) {
    int id = blockIdx.x * 256 + threadIdx.x;
    int r = id >> 11, c = id & 2047;
    int kb = r / HBLK_, o = r - kb * HBLK_;
    if (o >= 683) { F[id] = __float2bfloat16(0.f); return; }
    int jb = c >> 8, p = c & 255;
    int i = g_Ji[kb*8 + jb];
    float w = W[((size_t)i * 683 + o) * 256 + p];
    F[id] = __float2bfloat16(g_Sg[kb*8 + jb] * tsign(w, sc[i]));
}
// down: [C, HIDP2]  cols padded per 768-block
__global__ void build_tq_d_k(const float* __restrict__ W, const float* __restrict__ sc,
                             __nv_bfloat16* __restrict__ F) {
    int id = blockIdx.x * 256 + threadIdx.x;
    int r = id / HIDP2_, c = id - r * HIDP2_;
    int jb = c / HBLK_, p = c - jb * HBLK_;
    if (p >= 683) { F[id] = __float2bfloat16(0.f); return; }
    int kb = r >> 8, o = r & 255;
    int i = g_Ji[kb*8 + jb];
    float w = W[((size_t)i * 256 + o) * 683 + p];
    F[id] = __float2bfloat16(g_Sg[kb*8 + jb] * tsign(w, sc[i]));
}

// ---------------- rmsnorm -> bf16 hi/lo ----------------
__global__ void rmsnorm_k(const float* __restrict__ x, const float* __restrict__ w,
                          __nv_bfloat16* __restrict__ oh, __nv_bfloat16* __restrict__ ol) {
    int row = blockIdx.x;
    const float* xr = x + (size_t)row * C_;
    float s = 0.f;
    for (int c = threadIdx.x; c < C_; c += 256) { float v = xr[c]; s += v * v; }
    __shared__ float red[256];
    red[threadIdx.x] = s; __syncthreads();
    for (int st = 128; st > 0; st >>= 1) {
        if (threadIdx.x < st) red[threadIdx.x] += red[threadIdx.x + st];
        __syncthreads();
    }
    float inv = 1.0f / sqrtf(red[0] / (float)C_ + 1e-6f);
    for (int c = threadIdx.x; c < C_; c += 256) {
        float v = xr[c] * inv * w[c];
        split_store(v, oh + (size_t)row * C_ + c, ol + (size_t)row * C_ + c);
    }
}

// ---------------- 2-term deferred-scale mma GEMM ----------------
// C[M,N] = sum_jb s[kb,jb] * sum_{k in jb} (Ah + Al) @ Bq^T   (+addsrc)
// A: [M,K] bf16 hi/lo; Bq: [N,K] exact ternary bf16 (sign-folded).
// nblk: N-width of a scale block (256 or 768); kblk: K-width (256 or 768).
#define G_TILE_B 16384
#define G_STAGE  (3 * G_TILE_B)     // Ah | Al | B
#define G_NSTAGE 3
#define GSMEM_TOTAL (G_NSTAGE * G_STAGE)

__global__ __launch_bounds__(256, 1) void gemm2_k(
    const __nv_bfloat16* __restrict__ Ah, const __nv_bfloat16* __restrict__ Al,
    const __nv_bfloat16* __restrict__ Bq, const float* __restrict__ sctab,
    const float* __restrict__ addsrc, float* __restrict__ Cm,
    int M, int N, int K, int nblk, int kblk)
{
    extern __shared__ __align__(1024) char smem[];
    int tid = threadIdx.x, wid = tid >> 5, lane = tid & 31;
    int wr = wid >> 1, wc = wid & 1;
    int bm = blockIdx.y * 128, bn = blockIdx.x * 128;
    uint32_t sbase = smem_u32(smem);

    int kb = bn / nblk;
    const float* stab = sctab + kb * 8;
    int cpb = kblk >> 6;            // chunks per scale block
    int total = K >> 6;

    float part[2][8][4];
    float tot [2][8][4];
#pragma unroll
    for (int mt = 0; mt < 2; mt++)
#pragma unroll
        for (int nt = 0; nt < 8; nt++)
#pragma unroll
            for (int e = 0; e < 4; e++) { part[mt][nt][e] = 0.f; tot[mt][nt][e] = 0.f; }

    int a_row = ((lane >> 3) & 1) * 8 + (lane & 7);
    int a_kb  = (lane >> 4) * 16;
    int b_n   = ((lane >> 4) & 1) * 8 + (lane & 7);
    int b_kb  = ((lane >> 3) & 1) * 16;

#define ISSUE2(ch) do {                                                       \
        int k0_ = (ch) << 6;                                                  \
        uint32_t stg_ = sbase + ((ch) % 3) * G_STAGE;                         \
        _Pragma("unroll")                                                     \
        for (int u = 0; u < 4; u++) {                                         \
            int i_ = tid + u * 256;                                           \
            int row_ = i_ >> 3, seg_ = i_ & 7;                                \
            uint32_t so_ = SW128(row_ * 128 + seg_ * 16);                     \
            size_t  go_ = (size_t)(bm + row_) * K + k0_ + seg_ * 8;           \
            cp16(stg_ + so_, Ah + go_);                                       \
            cp16(stg_ + G_TILE_B + so_, Al + go_);                            \
            cp16(stg_ + 2 * G_TILE_B + so_,                                   \
                 Bq + (size_t)(bn + row_) * K + k0_ + seg_ * 8);              \
        }                                                                     \
        asm volatile("cp.async.commit_group;" ::: "memory");                  \
    } while (0)

    ISSUE2(0);
    if (total > 1) ISSUE2(1);
    for (int ch = 0; ch < total; ch++) {
        if (ch + 2 < total) {
            ISSUE2(ch + 2);
            asm volatile("cp.async.wait_group 2;" ::: "memory");
        } else if (ch + 1 < total) {
            asm volatile("cp.async.wait_group 1;" ::: "memory");
        } else {
            asm volatile("cp.async.wait_group 0;" ::: "memory");
        }
        __syncthreads();

        uint32_t stg = sbase + (ch % 3) * G_STAGE;
#pragma unroll
        for (int kk = 0; kk < 4; kk++) {
            uint32_t ah[2][4], al[2][4];
#pragma unroll
            for (int mt = 0; mt < 2; mt++) {
                uint32_t byte = (uint32_t)(wr * 32 + mt * 16 + a_row) * 128 + kk * 32 + a_kb;
                uint32_t so = SW128(byte);
                ldm_x4(stg + so, ah[mt][0], ah[mt][1], ah[mt][2], ah[mt][3]);
                ldm_x4(stg + G_TILE_B + so, al[mt][0], al[mt][1], al[mt][2], al[mt][3]);
            }
            uint32_t b[4][4];
#pragma unroll
            for (int np = 0; np < 4; np++) {
                uint32_t byte = (uint32_t)(wc * 64 + np * 16 + b_n) * 128 + kk * 32 + b_kb;
                ldm_x4(stg + 2 * G_TILE_B + SW128(byte), b[np][0], b[np][1], b[np][2], b[np][3]);
            }
#pragma unroll
            for (int mt = 0; mt < 2; mt++)
#pragma unroll
                for (int nt = 0; nt < 8; nt++) {
                    mma16816(part[mt][nt], ah[mt], b[nt >> 1][(nt & 1) * 2],
                             b[nt >> 1][(nt & 1) * 2 + 1]);
                    mma16816(part[mt][nt], al[mt], b[nt >> 1][(nt & 1) * 2],
                             b[nt >> 1][(nt & 1) * 2 + 1]);
                }
        }
        __syncthreads();

        if (((ch + 1) % cpb) == 0) {       // scale-block boundary
            float s = stab[ch / cpb];
#pragma unroll
            for (int mt = 0; mt < 2; mt++)
#pragma unroll
                for (int nt = 0; nt < 8; nt++)
#pragma unroll
                    for (int e = 0; e < 4; e++) {
                        tot[mt][nt][e] = fmaf(s, part[mt][nt][e], tot[mt][nt][e]);
                        part[mt][nt][e] = 0.f;
                    }
        }
    }

    // epilogue
#pragma unroll
    for (int mt = 0; mt < 2; mt++)
#pragma unroll
        for (int nt = 0; nt < 8; nt++) {
            int r0 = bm + wr * 32 + mt * 16 + (lane >> 2);
            int c  = bn + wc * 64 + nt * 8 + (lane & 3) * 2;
            size_t i0 = (size_t)r0 * N + c;
            size_t i1 = i0 + (size_t)8 * N;
            float2 v0 = make_float2(tot[mt][nt][0], tot[mt][nt][1]);
            float2 v1 = make_float2(tot[mt][nt][2], tot[mt][nt][3]);
            if (addsrc) {
                float2 s0 = *(const float2*)&addsrc[i0];
                float2 s1 = *(const float2*)&addsrc[i1];
                v0.x += s0.x; v0.y += s0.y;
                v1.x += s1.x; v1.y += s1.y;
            }
            *(float2*)&Cm[i0] = v0;
            *(float2*)&Cm[i1] = v1;
        }
}

// ---------------- RoPE ----------------
__global__ void rope_k(float* __restrict__ x, const float* __restrict__ cosb,
                       const float* __restrict__ sinb) {
    int id = blockIdx.x * 256 + threadIdx.x;
    int m = id >> 10;
    int pi = id & 1023;
    int h = pi >> 6, dp = pi & 63;
    int t = m & (T_ - 1);
    size_t base = (size_t)m * C_ + h * HD_ + 2 * dp;
    float xr = x[base], xi = x[base + 1];
    float cc = cosb[t * 64 + dp], ss = sinb[t * 64 + dp];
    x[base]     = xr * cc - xi * ss;
    x[base + 1] = xr * ss + xi * cc;
}

// ---------------- causal flash attention (fp32), writes bf16 hi/lo ----------------
#define ATT_LDQ 132
#define ATT_LDP 68
#define ATT_SMEM ((2 * 64 * ATT_LDQ + 64 * ATT_LDP) * 4)
__global__ __launch_bounds__(256) void attn_k(
    const float* __restrict__ q, const float* __restrict__ kmat,
    const float* __restrict__ v,
    __nv_bfloat16* __restrict__ yh, __nv_bfloat16* __restrict__ yl)
{
    extern __shared__ float sm[];
    float* Qs = sm;
    float* Ks = sm + 64 * ATT_LDQ;
    float* Ps = sm + 2 * 64 * ATT_LDQ;

    int bh = blockIdx.x, qt = blockIdx.y;
    int b = bh >> 4, h = bh & 15;
    int tid = threadIdx.x, r = tid >> 2, g = tid & 3;
    const float sc = 0.08838834764831845f;

    size_t qbase = ((size_t)(b * T_ + qt * 64)) * C_ + h * HD_;
    for (int i = tid; i < 64 * 32; i += 256) {
        int row = i >> 5, d4 = (i & 31) << 2;
        float4 val = *(const float4*)(q + qbase + (size_t)row * C_ + d4);
        val.x *= sc; val.y *= sc; val.z *= sc; val.w *= sc;
        *(float4*)&Qs[row * ATT_LDQ + d4] = val;
    }

    float m_run = -INFINITY, l_run = 0.f;
    float acc[32];
#pragma unroll
    for (int j = 0; j < 32; j++) acc[j] = 0.f;

    int qg = qt * 64 + r;
    for (int kt = 0; kt <= qt; kt++) {
        __syncthreads();
        size_t kbase = ((size_t)(b * T_ + kt * 64)) * C_ + h * HD_;
        for (int i = tid; i < 64 * 32; i += 256) {
            int row = i >> 5, d4 = (i & 31) << 2;
            *(float4*)&Ks[row * ATT_LDQ + d4] =
                *(const float4*)(kmat + kbase + (size_t)row * C_ + d4);
        }
        __syncthreads();

        float s[16];
#pragma unroll
        for (int j = 0; j < 16; j++) s[j] = 0.f;
        const float* qrow = &Qs[r * ATT_LDQ];
#pragma unroll 8
        for (int d = 0; d < 128; d++) {
            float qv = qrow[d];
#pragma unroll
            for (int j = 0; j < 16; j++)
                s[j] = fmaf(qv, Ks[(g + 4 * j) * ATT_LDQ + d], s[j]);
        }
        if (kt == qt) {
#pragma unroll
            for (int j = 0; j < 16; j++) {
                int kg = kt * 64 + g + 4 * j;
                if (kg > qg) s[j] = -1e30f;
            }
        }
        float tmax = s[0];
#pragma unroll
        for (int j = 1; j < 16; j++) tmax = fmaxf(tmax, s[j]);
        tmax = fmaxf(tmax, __shfl_xor_sync(0xffffffffu, tmax, 1));
        tmax = fmaxf(tmax, __shfl_xor_sync(0xffffffffu, tmax, 2));
        float m_new = fmaxf(m_run, tmax);
        float alpha = expf(m_run - m_new);
        float psum = 0.f;
#pragma unroll
        for (int j = 0; j < 16; j++) {
            float p = expf(s[j] - m_new);
            Ps[r * ATT_LDP + g + 4 * j] = p;
            psum += p;
        }
        psum += __shfl_xor_sync(0xffffffffu, psum, 1);
        psum += __shfl_xor_sync(0xffffffffu, psum, 2);
        l_run = l_run * alpha + psum;
        m_run = m_new;
#pragma unroll
        for (int j = 0; j < 32; j++) acc[j] *= alpha;

        __syncthreads();
        for (int i = tid; i < 64 * 32; i += 256) {
            int row = i >> 5, d4 = (i & 31) << 2;
            *(float4*)&Ks[row * ATT_LDQ + d4] =
                *(const float4*)(v + kbase + (size_t)row * C_ + d4);
        }
        __syncthreads();
#pragma unroll 4
        for (int kk = 0; kk < 64; kk++) {
            float p = Ps[r * ATT_LDP + kk];
            const float* vrow = &Ks[kk * ATT_LDQ];
#pragma unroll
            for (int j = 0; j < 32; j++)
                acc[j] = fmaf(p, vrow[g + 4 * j], acc[j]);
        }
    }

    float invl = 1.f / l_run;
#pragma unroll
    for (int j = 0; j < 32; j++) {
        float val = acc[j] * invl;
        size_t o = qbase + (size_t)r * C_ + g + 4 * j;
        split_store(val, yh + o, yl + o);
    }
}

// ---------------- silu(gate)*up -> bf16 hi/lo ----------------
__global__ void siluprod_k(const float* __restrict__ g, const float* __restrict__ u,
                           __nv_bfloat16* __restrict__ ph, __nv_bfloat16* __restrict__ pl) {
    size_t id = (size_t)blockIdx.x * 256 + threadIdx.x;
    float gv = g[id];
    float s = gv / (1.f + expf(-gv));
    split_store(s * u[id], ph + id, pl + id);
}

// ---------------- launch ----------------
extern "C" void kernel_launch(void* const* d_in, const int* in_sizes, int n_in,
                              void* d_out, int out_size) {
    const float* x   = (const float*)d_in[0];
    const float* fc  = (const float*)d_in[1];
    const float* fs  = (const float*)d_in[2];
    const float* anw = (const float*)d_in[3];
    const float* fnw = (const float*)d_in[4];
    const float* wq  = (const float*)d_in[5];
    const float* wk  = (const float*)d_in[6];
    const float* wv  = (const float*)d_in[7];
    const float* wo  = (const float*)d_in[8];
    const float* wg  = (const float*)d_in[9];
    const float* wu  = (const float*)d_in[10];
    const float* wd  = (const float*)d_in[11];
    float* out = (float*)d_out;

    __nv_bfloat16 *Wq,*Wk,*Wv,*Wo,*Wg,*Wu,*Wd;
    __nv_bfloat16 *XNh,*XNl,*Yh,*Yl,*HNh,*HNl,*PRh,*PRl;
    float *Q,*K,*V,*Hb,*GATE,*UP,*SC,*SCTAB;
    double* PART;
    cudaGetSymbolAddress((void**)&Wq, g_Wq);
    cudaGetSymbolAddress((void**)&Wk, g_Wk);
    cudaGetSymbolAddress((void**)&Wv, g_Wv);
    cudaGetSymbolAddress((void**)&Wo, g_Wo);
    cudaGetSymbolAddress((void**)&Wg, g_Wg);
    cudaGetSymbolAddress((void**)&Wu, g_Wu);
    cudaGetSymbolAddress((void**)&Wd, g_Wd);
    cudaGetSymbolAddress((void**)&XNh, g_XNh); cudaGetSymbolAddress((void**)&XNl, g_XNl);
    cudaGetSymbolAddress((void**)&Yh,  g_Yh);  cudaGetSymbolAddress((void**)&Yl,  g_Yl);
    cudaGetSymbolAddress((void**)&HNh, g_HNh); cudaGetSymbolAddress((void**)&HNl, g_HNl);
    cudaGetSymbolAddress((void**)&PRh, g_PRh); cudaGetSymbolAddress((void**)&PRl, g_PRl);
    cudaGetSymbolAddress((void**)&Q,  g_q);
    cudaGetSymbolAddress((void**)&K,  g_kk);
    cudaGetSymbolAddress((void**)&V,  g_v);
    cudaGetSymbolAddress((void**)&Hb, g_h);
    cudaGetSymbolAddress((void**)&GATE, g_gate);
    cudaGetSymbolAddress((void**)&UP, g_up);
    cudaGetSymbolAddress((void**)&SC, g_scale);
    cudaGetSymbolAddress((void**)&SCTAB, g_sctab);
    cudaGetSymbolAddress((void**)&PART, g_part);

    cudaFuncSetAttribute(attn_k, cudaFuncAttributeMaxDynamicSharedMemorySize, ATT_SMEM);
    cudaFuncSetAttribute(gemm2_k, cudaFuncAttributeMaxDynamicSharedMemorySize, GSMEM_TOTAL);

    build_tables_k<<<1, 1>>>();
    dim3 gsc(8, 8);
    scales_part_k<<<gsc, 256>>>(wq, 256*256, PART); scales_fin_k<<<1, 8>>>(PART, 256*256, SC + 0);
    scales_part_k<<<gsc, 256>>>(wk, 256*256, PART); scales_fin_k<<<1, 8>>>(PART, 256*256, SC + 8);
    scales_part_k<<<gsc, 256>>>(wv, 256*256, PART); scales_fin_k<<<1, 8>>>(PART, 256*256, SC + 16);
    scales_part_k<<<gsc, 256>>>(wo, 256*256, PART); scales_fin_k<<<1, 8>>>(PART, 256*256, SC + 24);
    scales_part_k<<<gsc, 256>>>(wg, 683*256, PART); scales_fin_k<<<1, 8>>>(PART, 683*256, SC + 32);
    scales_part_k<<<gsc, 256>>>(wu, 683*256, PART); scales_fin_k<<<1, 8>>>(PART, 683*256, SC + 40);
    scales_part_k<<<gsc, 256>>>(wd, 256*683, PART); scales_fin_k<<<1, 8>>>(PART, 256*683, SC + 48);
    build_sctab_k<<<1, 448>>>();

    build_tq_sq_k<<<(C_ * C_) / 256, 256>>>(wq, SC + 0,  Wq);
    build_tq_sq_k<<<(C_ * C_) / 256, 256>>>(wk, SC + 8,  Wk);
    build_tq_sq_k<<<(C_ * C_) / 256, 256>>>(wv, SC + 16, Wv);
    build_tq_sq_k<<<(C_ * C_) / 256, 256>>>(wo, SC + 24, Wo);
    build_tq_h_k<<<(HIDP2_ * C_) / 256, 256>>>(wg, SC + 32, Wg);
    build_tq_h_k<<<(HIDP2_ * C_) / 256, 256>>>(wu, SC + 40, Wu);
    build_tq_d_k<<<(C_ * HIDP2_) / 256, 256>>>(wd, SC + 48, Wd);

    rmsnorm_k<<<BT_, 256>>>(x, anw, XNh, XNl);

    dim3 gsq(C_ / 128, BT_ / 128);
    gemm2_k<<<gsq, 256, GSMEM_TOTAL>>>(XNh, XNl, Wq, SCTAB + 0,   nullptr, Q, BT_, C_, C_, 256, 256);
    gemm2_k<<<gsq, 256, GSMEM_TOTAL>>>(XNh, XNl, Wk, SCTAB + 64,  nullptr, K, BT_, C_, C_, 256, 256);
    gemm2_k<<<gsq, 256, GSMEM_TOTAL>>>(XNh, XNl, Wv, SCTAB + 128, nullptr, V, BT_, C_, C_, 256, 256);

    rope_k<<<(BT_ * 1024) / 256, 256>>>(Q, fc, fs);
    rope_k<<<(BT_ * 1024) / 256, 256>>>(K, fc, fs);

    attn_k<<<dim3(64, 16), 256, ATT_SMEM>>>(Q, K, V, Yh, Yl);

    gemm2_k<<<gsq, 256, GSMEM_TOTAL>>>(Yh, Yl, Wo, SCTAB + 192, x, Hb, BT_, C_, C_, 256, 256);
    rmsnorm_k<<<BT_, 256>>>(Hb, fnw, HNh, HNl);

    dim3 gh(HIDP2_ / 128, BT_ / 128);
    gemm2_k<<<gh, 256, GSMEM_TOTAL>>>(HNh, HNl, Wg, SCTAB + 256, nullptr, GATE, BT_, HIDP2_, C_, 768, 256);
    gemm2_k<<<gh, 256, GSMEM_TOTAL>>>(HNh, HNl, Wu, SCTAB + 320, nullptr, UP,   BT_, HIDP2_, C_, 768, 256);

    siluprod_k<<<(int)(((size_t)BT_ * HIDP2_) / 256), 256>>>(GATE, UP, PRh, PRl);

    gemm2_k<<<gsq, 256, GSMEM_TOTAL>>>(PRh, PRl, Wd, SCTAB + 384, Hb, out, BT_, C_, HIDP2_, 256, 768);
}

// round 6
// speedup vs baseline: 4.1025x; 1.5516x over previous
#include <cuda_runtime.h>
#include <cuda_bf16.h>
#include <cuda_fp16.h>
#include <math.h>
#include <stdint.h>

// ---------------- problem constants ----------------
#define BT_    4096          // B*T
#define C_     2048
#define T_     1024
#define H_     16
#define HD_    128
#define HID_   5464
#define HBLK_  688           // padded hidden block
#define HIDP_  5504          // 8*688 = 43*128 = 86*64
#define NQKV_  6144
#define NGU_   11008         // 2*5504

// ---------------- helpers ----------------
__device__ __forceinline__ uint32_t smem_u32(const void* p) {
    uint32_t a;
    asm("{ .reg .u64 t; cvta.to.shared.u64 t, %1; cvt.u32.u64 %0, t; }" : "=r"(a) : "l"(p));
    return a;
}
#define SW128(o) ((o) ^ (((o) >> 3) & 0x70))

__device__ __forceinline__ void cp16(uint32_t s, const void* g) {
    asm volatile("cp.async.cg.shared.global [%0], [%1], 16;"
                 :: "r"(s), "l"(__cvta_generic_to_global(g)));
}
__device__ __forceinline__ void ldm_x4(uint32_t addr, uint32_t& r0, uint32_t& r1,
                                       uint32_t& r2, uint32_t& r3) {
    asm volatile("ldmatrix.sync.aligned.m8n8.x4.shared.b16 {%0,%1,%2,%3}, [%4];"
                 : "=r"(r0), "=r"(r1), "=r"(r2), "=r"(r3) : "r"(addr));
}
__device__ __forceinline__ void mma16816h(float* c, const uint32_t* a, uint32_t b0, uint32_t b1) {
    asm volatile(
        "mma.sync.aligned.m16n8k16.row.col.f32.f16.f16.f32 "
        "{%0,%1,%2,%3}, {%4,%5,%6,%7}, {%8,%9}, {%0,%1,%2,%3};"
        : "+f"(c[0]), "+f"(c[1]), "+f"(c[2]), "+f"(c[3])
        : "r"(a[0]), "r"(a[1]), "r"(a[2]), "r"(a[3]), "r"(b0), "r"(b1));
}

// ---------------- scratch (device globals, no allocs) ----------------
__device__ __half g_Wqkv[(size_t)NQKV_*C_];
__device__ __half g_Wo  [(size_t)C_*C_];
__device__ __half g_Wgu [(size_t)NGU_*C_];
__device__ __half g_Wd  [(size_t)C_*HIDP_];
__device__ __half g_XN  [(size_t)BT_*C_];
__device__ __half g_Y   [(size_t)BT_*C_];
__device__ __half g_HN  [(size_t)BT_*C_];
__device__ __half g_GU  [(size_t)BT_*NGU_];
__device__ __half g_PR  [(size_t)BT_*HIDP_];
__device__ float  g_QKV [(size_t)BT_*NQKV_];
__device__ float  g_Hb  [(size_t)BT_*C_];
__device__ int    g_Ji[64];
__device__ float  g_Sg[64];
__device__ float  g_scale[56];
__device__ double g_part[7*8*8];

struct ScaleSrc { const float* p[7]; int op[7]; };

// ---------------- octonion table ----------------
__global__ void build_tables_k() {
    int idx[8][8]; float sg[8][8];
    for (int j = 0; j < 8; j++) { idx[0][j] = j; sg[0][j] = 1.f; }
    for (int i = 1; i < 8; i++) {
        idx[i][0] = i; sg[i][0] = 1.f;
        idx[i][i] = 0; sg[i][i] = -1.f;
    }
    const int tr[7][3] = {{1,2,3},{1,4,5},{1,7,6},{2,4,6},{2,5,7},{3,4,7},{3,6,5}};
    for (int t = 0; t < 7; t++) {
        int a = tr[t][0], b = tr[t][1], c = tr[t][2];
        int per[3][3] = {{a,b,c},{b,c,a},{c,a,b}};
        for (int u = 0; u < 3; u++) {
            int p = per[u][0], q = per[u][1], r = per[u][2];
            idx[p][q] = r; sg[p][q] = 1.f;
            idx[q][p] = r; sg[q][p] = -1.f;
        }
    }
    for (int i = 0; i < 8; i++)
        for (int j = 0; j < 8; j++) {
            int k = idx[i][j];
            g_Ji[k*8 + j] = i;
            g_Sg[k*8 + j] = sg[i][j];
        }
}

// ---------------- scales: fused over all 7 tensors ----------------
__global__ void scales_part_k(ScaleSrc ss) {
    int t = blockIdx.z, i = blockIdx.x, sl = blockIdx.y;
    int OP = ss.op[t];
    const float* Wi = ss.p[t] + (size_t)i * OP;
    int per = (OP + 7) / 8;
    int st = sl * per, en = min(OP, st + per);
    double s = 0.0;
    for (int u = st + threadIdx.x; u < en; u += 256) s += (double)fabsf(Wi[u]);
    __shared__ double red[256];
    red[threadIdx.x] = s; __syncthreads();
    for (int stp = 128; stp > 0; stp >>= 1) {
        if (threadIdx.x < stp) red[threadIdx.x] += red[threadIdx.x + stp];
        __syncthreads();
    }
    if (threadIdx.x == 0) g_part[(t*8 + i)*8 + sl] = red[0];
}
__global__ void scales_fin_k(ScaleSrc ss) {
    int id = threadIdx.x;           // 56
    int t = id >> 3, i = id & 7;
    double s = 0.0;
    for (int j = 0; j < 8; j++) s += g_part[(t*8 + i)*8 + j];
    g_scale[id] = (float)(s / (double)ss.op[t]);
}

__device__ __forceinline__ float tsign(float w, float s) {
    float q = rintf(w / (s + 1e-8f));
    return fmaxf(-1.f, fminf(1.f, q));
}

// ---------------- weight builds: fp16, scale folded ----------------
// QKV merged: [6144, 2048], rows 0-2047 q, 2048-4095 k, 4096-6143 v
__global__ void build_qkv_k(const float* __restrict__ wq, const float* __restrict__ wk,
                            const float* __restrict__ wv, __half* __restrict__ F) {
    int id = blockIdx.x * 256 + threadIdx.x;
    int r = id >> 11, c = id & 2047;
    int t = r >> 11, rr = r & 2047;
    int kb = rr >> 8, o = rr & 255, jb = c >> 8, p = c & 255;
    int i = g_Ji[kb*8 + jb];
    const float* src = (t == 0) ? wq : ((t == 1) ? wk : wv);
    float s = g_scale[t*8 + i];
    float w = src[((size_t)i << 16) + (o << 8) + p];
    F[id] = __float2half(g_Sg[kb*8 + jb] * tsign(w, s) * s);
}
__global__ void build_wo_k(const float* __restrict__ wo, __half* __restrict__ F) {
    int id = blockIdx.x * 256 + threadIdx.x;
    int r = id >> 11, c = id & 2047;
    int kb = r >> 8, o = r & 255, jb = c >> 8, p = c & 255;
    int i = g_Ji[kb*8 + jb];
    float s = g_scale[24 + i];
    float w = wo[((size_t)i << 16) + (o << 8) + p];
    F[id] = __float2half(g_Sg[kb*8 + jb] * tsign(w, s) * s);
}
// GU merged: [11008, 2048], rows 0-5503 gate, 5504-11007 up; hidden blocks of 688 (683 valid)
__global__ void build_gu_k(const float* __restrict__ wg, const float* __restrict__ wu,
                           __half* __restrict__ F) {
    int id = blockIdx.x * 256 + threadIdx.x;
    int r = id >> 11, c = id & 2047;
    int t = r / HIDP_, ro = r - t * HIDP_;
    int kb = ro / HBLK_, o = ro - kb * HBLK_;
    if (o >= 683) { F[id] = __float2half(0.f); return; }
    int jb = c >> 8, p = c & 255;
    int i = g_Ji[kb*8 + jb];
    const float* src = t ? wu : wg;
    float s = g_scale[32 + t*8 + i];
    float w = src[((size_t)i * 683 + o) * 256 + p];
    F[id] = __float2half(g_Sg[kb*8 + jb] * tsign(w, s) * s);
}
// down: [2048, 5504]; col blocks of 688 (683 valid)
__global__ void build_d_k(const float* __restrict__ wd, __half* __restrict__ F) {
    int id = blockIdx.x * 256 + threadIdx.x;
    int r = id / HIDP_, c = id - r * HIDP_;
    int jb = c / HBLK_, p = c - jb * HBLK_;
    if (p >= 683) { F[id] = __float2half(0.f); return; }
    int kb = r >> 8, o = r & 255;
    int i = g_Ji[kb*8 + jb];
    float s = g_scale[48 + i];
    float w = wd[((size_t)i * 256 + o) * 683 + p];
    F[id] = __float2half(g_Sg[kb*8 + jb] * tsign(w, s) * s);
}

// ---------------- rmsnorm -> fp16 ----------------
__global__ void rmsnorm_k(const float* __restrict__ x, const float* __restrict__ w,
                          __half* __restrict__ oh) {
    int row = blockIdx.x;
    const float* xr = x + (size_t)row * C_;
    float s = 0.f;
    for (int c = threadIdx.x; c < C_; c += 256) { float v = xr[c]; s += v * v; }
    __shared__ float red[256];
    red[threadIdx.x] = s; __syncthreads();
    for (int st = 128; st > 0; st >>= 1) {
        if (threadIdx.x < st) red[threadIdx.x] += red[threadIdx.x + st];
        __syncthreads();
    }
    float inv = 1.0f / sqrtf(red[0] / (float)C_ + 1e-6f);
    for (int c = threadIdx.x; c < C_; c += 256)
        oh[(size_t)row * C_ + c] = __float2half(xr[c] * inv * w[c]);
}

// ---------------- fp16 single-term GEMM, 128x256 tile ----------------
// C[M,N] = A[M,K] @ B[N,K]^T (+addsrc), all fp16 in, fp32 accum.
#define G1_ABYTES 16384
#define G1_STAGE  49152    // A 16KB | B 32KB
#define G1_SMEM   (3 * G1_STAGE)

__device__ __forceinline__ void store2(float* C, size_t i, float x, float y, const float* add) {
    if (add) { const float2 a = *(const float2*)&add[i]; x += a.x; y += a.y; }
    *(float2*)&C[i] = make_float2(x, y);
}
__device__ __forceinline__ void store2(__half* C, size_t i, float x, float y, const float* add) {
    *(__half2*)&C[i] = __floats2half2_rn(x, y);
}

template<typename OutT>
__global__ __launch_bounds__(256, 1) void gemm1_k(
    const __half* __restrict__ A, const __half* __restrict__ B,
    const float* __restrict__ addsrc, OutT* __restrict__ Cm,
    int M, int N, int K)
{
    extern __shared__ __align__(1024) char smem[];
    int tid = threadIdx.x, wid = tid >> 5, lane = tid & 31;
    int wr = wid >> 1, wc = wid & 1;
    int bm = blockIdx.y * 128, bn = blockIdx.x * 256;
    uint32_t sbase = smem_u32(smem);
    int total = K >> 6;

    float acc[2][16][4];
#pragma unroll
    for (int mt = 0; mt < 2; mt++)
#pragma unroll
        for (int nt = 0; nt < 16; nt++)
#pragma unroll
            for (int e = 0; e < 4; e++) acc[mt][nt][e] = 0.f;

    int a_row = ((lane >> 3) & 1) * 8 + (lane & 7);
    int a_kb  = (lane >> 4) * 16;
    int b_n   = ((lane >> 4) & 1) * 8 + (lane & 7);
    int b_kb  = ((lane >> 3) & 1) * 16;

#define ISSUE1(ch) do {                                                       \
        int k0_ = (ch) << 6;                                                  \
        uint32_t stg_ = sbase + ((ch) % 3) * G1_STAGE;                        \
        _Pragma("unroll")                                                     \
        for (int u = 0; u < 4; u++) {                                         \
            int i_ = tid + u * 256;                                           \
            int row_ = i_ >> 3, seg_ = i_ & 7;                                \
            cp16(stg_ + SW128(row_ * 128 + seg_ * 16),                        \
                 A + (size_t)(bm + row_) * K + k0_ + seg_ * 8);               \
        }                                                                     \
        _Pragma("unroll")                                                     \
        for (int u = 0; u < 8; u++) {                                         \
            int i_ = tid + u * 256;                                           \
            int row_ = i_ >> 3, seg_ = i_ & 7;                                \
            cp16(stg_ + G1_ABYTES + SW128(row_ * 128 + seg_ * 16),            \
                 B + (size_t)(bn + row_) * K + k0_ + seg_ * 8);               \
        }                                                                     \
        asm volatile("cp.async.commit_group;" ::: "memory");                  \
    } while (0)

    ISSUE1(0);
    if (total > 1) ISSUE1(1);
    for (int ch = 0; ch < total; ch++) {
        if (ch + 2 < total) {
            ISSUE1(ch + 2);
            asm volatile("cp.async.wait_group 2;" ::: "memory");
        } else if (ch + 1 < total) {
            asm volatile("cp.async.wait_group 1;" ::: "memory");
        } else {
            asm volatile("cp.async.wait_group 0;" ::: "memory");
        }
        __syncthreads();

        uint32_t stg = sbase + (ch % 3) * G1_STAGE;
#pragma unroll
        for (int kk = 0; kk < 4; kk++) {
            uint32_t a[2][4];
#pragma unroll
            for (int mt = 0; mt < 2; mt++) {
                uint32_t byte = (uint32_t)(wr * 32 + mt * 16 + a_row) * 128 + kk * 32 + a_kb;
                ldm_x4(stg + SW128(byte), a[mt][0], a[mt][1], a[mt][2], a[mt][3]);
            }
            uint32_t b[8][4];
#pragma unroll
            for (int np = 0; np < 8; np++) {
                uint32_t byte = (uint32_t)(wc * 128 + np * 16 + b_n) * 128 + kk * 32 + b_kb;
                ldm_x4(stg + G1_ABYTES + SW128(byte), b[np][0], b[np][1], b[np][2], b[np][3]);
            }
#pragma unroll
            for (int mt = 0; mt < 2; mt++)
#pragma unroll
                for (int nt = 0; nt < 16; nt++)
                    mma16816h(acc[mt][nt], a[mt], b[nt >> 1][(nt & 1) * 2],
                              b[nt >> 1][(nt & 1) * 2 + 1]);
        }
        __syncthreads();
    }

#pragma unroll
    for (int mt = 0; mt < 2; mt++)
#pragma unroll
        for (int nt = 0; nt < 16; nt++) {
            int r0 = bm + wr * 32 + mt * 16 + (lane >> 2);
            int c  = bn + wc * 128 + nt * 8 + (lane & 3) * 2;
            size_t i0 = (size_t)r0 * N + c;
            size_t i1 = i0 + (size_t)8 * N;
            store2(Cm, i0, acc[mt][nt][0], acc[mt][nt][1], addsrc);
            store2(Cm, i1, acc[mt][nt][2], acc[mt][nt][3], addsrc);
        }
}

// ---------------- RoPE on merged QKV (Q cols 0-2047, K cols 2048-4095) ----------------
__global__ void rope_k(float* __restrict__ x, const float* __restrict__ cosb,
                       const float* __restrict__ sinb) {
    int id = blockIdx.x * 256 + threadIdx.x;    // BT_*2048 pairs
    int m = id >> 11;
    int pi = id & 2047;
    int h = pi >> 6, dp = pi & 63;              // h 0..31 (Q heads + K heads)
    int t = m & (T_ - 1);
    size_t base = (size_t)m * NQKV_ + h * HD_ + 2 * dp;
    float xr = x[base], xi = x[base + 1];
    float cc = cosb[t * 64 + dp], ss = sinb[t * 64 + dp];
    x[base]     = xr * cc - xi * ss;
    x[base + 1] = xr * ss + xi * cc;
}

// ---------------- causal flash attention (fp32) -> fp16 y ----------------
#define ATT_LDQ 132
#define ATT_LDP 68
#define ATT_SMEM ((2 * 64 * ATT_LDQ + 64 * ATT_LDP) * 4)
__global__ __launch_bounds__(256) void attn_k(
    const float* __restrict__ qkv, __half* __restrict__ y)
{
    extern __shared__ float sm[];
    float* Qs = sm;
    float* Ks = sm + 64 * ATT_LDQ;
    float* Ps = sm + 2 * 64 * ATT_LDQ;

    int bh = blockIdx.x, qt = blockIdx.y;
    int b = bh >> 4, h = bh & 15;
    int tid = threadIdx.x, r = tid >> 2, g = tid & 3;
    const float sc = 0.08838834764831845f;

    size_t qbase = ((size_t)(b * T_ + qt * 64)) * NQKV_ + h * HD_;
    for (int i = tid; i < 64 * 32; i += 256) {
        int row = i >> 5, d4 = (i & 31) << 2;
        float4 val = *(const float4*)(qkv + qbase + (size_t)row * NQKV_ + d4);
        val.x *= sc; val.y *= sc; val.z *= sc; val.w *= sc;
        *(float4*)&Qs[row * ATT_LDQ + d4] = val;
    }

    float m_run = -INFINITY, l_run = 0.f;
    float acc[32];
#pragma unroll
    for (int j = 0; j < 32; j++) acc[j] = 0.f;

    int qg = qt * 64 + r;
    for (int kt = 0; kt <= qt; kt++) {
        __syncthreads();
        size_t kbase = ((size_t)(b * T_ + kt * 64)) * NQKV_ + h * HD_ + 2048;
        for (int i = tid; i < 64 * 32; i += 256) {
            int row = i >> 5, d4 = (i & 31) << 2;
            *(float4*)&Ks[row * ATT_LDQ + d4] =
                *(const float4*)(qkv + kbase + (size_t)row * NQKV_ + d4);
        }
        __syncthreads();

        float s[16];
#pragma unroll
        for (int j = 0; j < 16; j++) s[j] = 0.f;
        const float* qrow = &Qs[r * ATT_LDQ];
#pragma unroll 8
        for (int d = 0; d < 128; d++) {
            float qv = qrow[d];
#pragma unroll
            for (int j = 0; j < 16; j++)
                s[j] = fmaf(qv, Ks[(g + 4 * j) * ATT_LDQ + d], s[j]);
        }
        if (kt == qt) {
#pragma unroll
            for (int j = 0; j < 16; j++) {
                int kg = kt * 64 + g + 4 * j;
                if (kg > qg) s[j] = -1e30f;
            }
        }
        float tmax = s[0];
#pragma unroll
        for (int j = 1; j < 16; j++) tmax = fmaxf(tmax, s[j]);
        tmax = fmaxf(tmax, __shfl_xor_sync(0xffffffffu, tmax, 1));
        tmax = fmaxf(tmax, __shfl_xor_sync(0xffffffffu, tmax, 2));
        float m_new = fmaxf(m_run, tmax);
        float alpha = expf(m_run - m_new);
        float psum = 0.f;
#pragma unroll
        for (int j = 0; j < 16; j++) {
            float p = expf(s[j] - m_new);
            Ps[r * ATT_LDP + g + 4 * j] = p;
            psum += p;
        }
        psum += __shfl_xor_sync(0xffffffffu, psum, 1);
        psum += __shfl_xor_sync(0xffffffffu, psum, 2);
        l_run = l_run * alpha + psum;
        m_run = m_new;
#pragma unroll
        for (int j = 0; j < 32; j++) acc[j] *= alpha;

        __syncthreads();
        size_t vbase = kbase + 2048;
        for (int i = tid; i < 64 * 32; i += 256) {
            int row = i >> 5, d4 = (i & 31) << 2;
            *(float4*)&Ks[row * ATT_LDQ + d4] =
                *(const float4*)(qkv + vbase + (size_t)row * NQKV_ + d4);
        }
        __syncthreads();
#pragma unroll 4
        for (int kk = 0; kk < 64; kk++) {
            float p = Ps[r * ATT_LDP + kk];
            const float* vrow = &Ks[kk * ATT_LDQ];
#pragma unroll
            for (int j = 0; j < 32; j++)
                acc[j] = fmaf(p, vrow[g + 4 * j], acc[j]);
        }
    }

    float invl = 1.f / l_run;
    size_t ybase = ((size_t)(b * T_ + qt * 64 + r)) * C_ + h * HD_;
#pragma unroll
    for (int j = 0; j < 32; j++)
        y[ybase + g + 4 * j] = __float2half(acc[j] * invl);
}

// ---------------- silu(gate)*up -> fp16 (half2) ----------------
__global__ void siluprod_k(const __half* __restrict__ gu, __half* __restrict__ pr) {
    size_t id = (size_t)blockIdx.x * 256 + threadIdx.x;   // BT_*2752
    size_t row = id / 2752;
    int c2 = (int)(id - row * 2752) * 2;
    size_t base = row * NGU_;
    float2 gv = __half22float2(*(const __half2*)&gu[base + c2]);
    float2 uv = __half22float2(*(const __half2*)&gu[base + HIDP_ + c2]);
    float p0 = gv.x / (1.f + expf(-gv.x)) * uv.x;
    float p1 = gv.y / (1.f + expf(-gv.y)) * uv.y;
    *(__half2*)&pr[row * HIDP_ + c2] = __floats2half2_rn(p0, p1);
}

// ---------------- launch ----------------
extern "C" void kernel_launch(void* const* d_in, const int* in_sizes, int n_in,
                              void* d_out, int out_size) {
    const float* x   = (const float*)d_in[0];
    const float* fc  = (const float*)d_in[1];
    const float* fs  = (const float*)d_in[2];
    const float* anw = (const float*)d_in[3];
    const float* fnw = (const float*)d_in[4];
    const float* wq  = (const float*)d_in[5];
    const float* wk  = (const float*)d_in[6];
    const float* wv  = (const float*)d_in[7];
    const float* wo  = (const float*)d_in[8];
    const float* wg  = (const float*)d_in[9];
    const float* wu  = (const float*)d_in[10];
    const float* wd  = (const float*)d_in[11];
    float* out = (float*)d_out;

    __half *Wqkv, *Wo, *Wgu, *Wd, *XN, *Y, *HN, *GU, *PR;
    float *QKV, *Hb;
    cudaGetSymbolAddress((void**)&Wqkv, g_Wqkv);
    cudaGetSymbolAddress((void**)&Wo,   g_Wo);
    cudaGetSymbolAddress((void**)&Wgu,  g_Wgu);
    cudaGetSymbolAddress((void**)&Wd,   g_Wd);
    cudaGetSymbolAddress((void**)&XN,   g_XN);
    cudaGetSymbolAddress((void**)&Y,    g_Y);
    cudaGetSymbolAddress((void**)&HN,   g_HN);
    cudaGetSymbolAddress((void**)&GU,   g_GU);
    cudaGetSymbolAddress((void**)&PR,   g_PR);
    cudaGetSymbolAddress((void**)&QKV,  g_QKV);
    cudaGetSymbolAddress((void**)&Hb,   g_Hb);

    cudaFuncSetAttribute(attn_k, cudaFuncAttributeMaxDynamicSharedMemorySize, ATT_SMEM);
    cudaFuncSetAttribute(gemm1_k<float>, cudaFuncAttributeMaxDynamicSharedMemorySize, G1_SMEM);
    cudaFuncSetAttribute(gemm1_k<__half>, cudaFuncAttributeMaxDynamicSharedMemorySize, G1_SMEM);

    build_tables_k<<<1, 1>>>();

    ScaleSrc ss;
    ss.p[0] = wq; ss.p[1] = wk; ss.p[2] = wv; ss.p[3] = wo;
    ss.p[4] = wg; ss.p[5] = wu; ss.p[6] = wd;
    ss.op[0] = ss.op[1] = ss.op[2] = ss.op[3] = 65536;
    ss.op[4] = ss.op[5] = ss.op[6] = 683 * 256;
    scales_part_k<<<dim3(8, 8, 7), 256>>>(ss);
    scales_fin_k<<<1, 56>>>(ss);

    build_qkv_k<<<(NQKV_ * C_) / 256, 256>>>(wq, wk, wv, Wqkv);
    build_wo_k<<<(C_ * C_) / 256, 256>>>(wo, Wo);
    build_gu_k<<<(NGU_ * C_) / 256, 256>>>(wg, wu, Wgu);
    build_d_k<<<(C_ * HIDP_) / 256, 256>>>(wd, Wd);

    rmsnorm_k<<<BT_, 256>>>(x, anw, XN);

    gemm1_k<float><<<dim3(NQKV_ / 256, BT_ / 128), 256, G1_SMEM>>>(
        XN, Wqkv, nullptr, QKV, BT_, NQKV_, C_);

    rope_k<<<(BT_ * 2048) / 256, 256>>>(QKV, fc, fs);

    attn_k<<<dim3(64, 16), 256, ATT_SMEM>>>(QKV, Y);

    gemm1_k<float><<<dim3(C_ / 256, BT_ / 128), 256, G1_SMEM>>>(
        Y, Wo, x, Hb, BT_, C_, C_);

    rmsnorm_k<<<BT_, 256>>>(Hb, fnw, HN);

    gemm1_k<__half><<<dim3(NGU_ / 256, BT_ / 128), 256, G1_SMEM>>>(
        HN, Wgu, nullptr, GU, BT_, NGU_, C_);

    siluprod_k<<<(BT_ * 2752) / 256, 256>>>(GU, PR);

    gemm1_k<float><<<dim3(C_ / 256, BT_ / 128), 256, G1_SMEM>>>(
        PR, Wd, Hb, out, BT_, C_, HIDP_);
}

// round 7
// speedup vs baseline: 7.2229x; 1.7606x over previous
#include <cuda_runtime.h>
#include <cuda_bf16.h>
#include <cuda_fp16.h>
#include <math.h>
#include <stdint.h>

// ---------------- problem constants ----------------
#define BT_    4096          // B*T
#define C_     2048
#define T_     1024
#define H_     16
#define HD_    128
#define HID_   5464
#define HBLK_  688           // padded hidden block
#define HIDP_  5504          // 8*688 = 43*128 = 86*64
#define NQKV_  6144
#define NGU_   11008         // 2*5504

// ---------------- helpers ----------------
__device__ __forceinline__ uint32_t smem_u32(const void* p) {
    uint32_t a;
    asm("{ .reg .u64 t; cvta.to.shared.u64 t, %1; cvt.u32.u64 %0, t; }" : "=r"(a) : "l"(p));
    return a;
}
#define SW128(o) ((o) ^ (((o) >> 3) & 0x70))          // 128B-row swizzle
#define SWK(o)   ((o) ^ ((((o) >> 8) & 7) << 4))      // 256B-row swizzle

__device__ __forceinline__ void cp16(uint32_t s, const void* g) {
    asm volatile("cp.async.cg.shared.global [%0], [%1], 16;"
                 :: "r"(s), "l"(__cvta_generic_to_global(g)));
}
__device__ __forceinline__ void ldm_x4(uint32_t addr, uint32_t& r0, uint32_t& r1,
                                       uint32_t& r2, uint32_t& r3) {
    asm volatile("ldmatrix.sync.aligned.m8n8.x4.shared.b16 {%0,%1,%2,%3}, [%4];"
                 : "=r"(r0), "=r"(r1), "=r"(r2), "=r"(r3) : "r"(addr));
}
__device__ __forceinline__ void ldm_x4t(uint32_t addr, uint32_t& r0, uint32_t& r1,
                                        uint32_t& r2, uint32_t& r3) {
    asm volatile("ldmatrix.sync.aligned.m8n8.x4.trans.shared.b16 {%0,%1,%2,%3}, [%4];"
                 : "=r"(r0), "=r"(r1), "=r"(r2), "=r"(r3) : "r"(addr));
}
__device__ __forceinline__ void mma16816h(float* c, const uint32_t* a, uint32_t b0, uint32_t b1) {
    asm volatile(
        "mma.sync.aligned.m16n8k16.row.col.f32.f16.f16.f32 "
        "{%0,%1,%2,%3}, {%4,%5,%6,%7}, {%8,%9}, {%0,%1,%2,%3};"
        : "+f"(c[0]), "+f"(c[1]), "+f"(c[2]), "+f"(c[3])
        : "r"(a[0]), "r"(a[1]), "r"(a[2]), "r"(a[3]), "r"(b0), "r"(b1));
}
__device__ __forceinline__ uint32_t packh2(float x, float y) {
    __half2 h = __floats2half2_rn(x, y);
    return *(uint32_t*)&h;
}

// ---------------- scratch (device globals, no allocs) ----------------
__device__ __half g_Wqkv[(size_t)NQKV_*C_];
__device__ __half g_Wo  [(size_t)C_*C_];
__device__ __half g_Wgu [(size_t)NGU_*C_];
__device__ __half g_Wd  [(size_t)C_*HIDP_];
__device__ __half g_XN  [(size_t)BT_*C_];
__device__ __half g_Y   [(size_t)BT_*C_];
__device__ __half g_HN  [(size_t)BT_*C_];
__device__ __half g_GU  [(size_t)BT_*NGU_];
__device__ __half g_PR  [(size_t)BT_*HIDP_];
__device__ __half g_QKV [(size_t)BT_*NQKV_];
__device__ float  g_Hb  [(size_t)BT_*C_];
__device__ int    g_Ji[64];
__device__ float  g_Sg[64];
__device__ float  g_scale[56];
__device__ double g_part[7*8*8];

struct ScaleSrc { const float* p[7]; int op[7]; };

// ---------------- octonion table ----------------
__global__ void build_tables_k() {
    int idx[8][8]; float sg[8][8];
    for (int j = 0; j < 8; j++) { idx[0][j] = j; sg[0][j] = 1.f; }
    for (int i = 1; i < 8; i++) {
        idx[i][0] = i; sg[i][0] = 1.f;
        idx[i][i] = 0; sg[i][i] = -1.f;
    }
    const int tr[7][3] = {{1,2,3},{1,4,5},{1,7,6},{2,4,6},{2,5,7},{3,4,7},{3,6,5}};
    for (int t = 0; t < 7; t++) {
        int a = tr[t][0], b = tr[t][1], c = tr[t][2];
        int per[3][3] = {{a,b,c},{b,c,a},{c,a,b}};
        for (int u = 0; u < 3; u++) {
            int p = per[u][0], q = per[u][1], r = per[u][2];
            idx[p][q] = r; sg[p][q] = 1.f;
            idx[q][p] = r; sg[q][p] = -1.f;
        }
    }
    for (int i = 0; i < 8; i++)
        for (int j = 0; j < 8; j++) {
            int k = idx[i][j];
            g_Ji[k*8 + j] = i;
            g_Sg[k*8 + j] = sg[i][j];
        }
}

// ---------------- scales ----------------
__global__ void scales_part_k(ScaleSrc ss) {
    int t = blockIdx.z, i = blockIdx.x, sl = blockIdx.y;
    int OP = ss.op[t];
    const float* Wi = ss.p[t] + (size_t)i * OP;
    int per = (OP + 7) / 8;
    int st = sl * per, en = min(OP, st + per);
    double s = 0.0;
    for (int u = st + threadIdx.x; u < en; u += 256) s += (double)fabsf(Wi[u]);
    __shared__ double red[256];
    red[threadIdx.x] = s; __syncthreads();
    for (int stp = 128; stp > 0; stp >>= 1) {
        if (threadIdx.x < stp) red[threadIdx.x] += red[threadIdx.x + stp];
        __syncthreads();
    }
    if (threadIdx.x == 0) g_part[(t*8 + i)*8 + sl] = red[0];
}
__global__ void scales_fin_k(ScaleSrc ss) {
    int id = threadIdx.x;
    int t = id >> 3, i = id & 7;
    double s = 0.0;
    for (int j = 0; j < 8; j++) s += g_part[(t*8 + i)*8 + j];
    g_scale[id] = (float)(s / (double)ss.op[t]);
}

__device__ __forceinline__ float tsign(float w, float s) {
    float q = rintf(w / (s + 1e-8f));
    return fmaxf(-1.f, fminf(1.f, q));
}

// ---------------- weight builds: fp16, scale folded ----------------
__global__ void build_qkv_k(const float* __restrict__ wq, const float* __restrict__ wk,
                            const float* __restrict__ wv, __half* __restrict__ F) {
    int id = blockIdx.x * 256 + threadIdx.x;
    int r = id >> 11, c = id & 2047;
    int t = r >> 11, rr = r & 2047;
    int kb = rr >> 8, o = rr & 255, jb = c >> 8, p = c & 255;
    int i = g_Ji[kb*8 + jb];
    const float* src = (t == 0) ? wq : ((t == 1) ? wk : wv);
    float s = g_scale[t*8 + i];
    float w = src[((size_t)i << 16) + (o << 8) + p];
    F[id] = __float2half(g_Sg[kb*8 + jb] * tsign(w, s) * s);
}
__global__ void build_wo_k(const float* __restrict__ wo, __half* __restrict__ F) {
    int id = blockIdx.x * 256 + threadIdx.x;
    int r = id >> 11, c = id & 2047;
    int kb = r >> 8, o = r & 255, jb = c >> 8, p = c & 255;
    int i = g_Ji[kb*8 + jb];
    float s = g_scale[24 + i];
    float w = wo[((size_t)i << 16) + (o << 8) + p];
    F[id] = __float2half(g_Sg[kb*8 + jb] * tsign(w, s) * s);
}
__global__ void build_gu_k(const float* __restrict__ wg, const float* __restrict__ wu,
                           __half* __restrict__ F) {
    int id = blockIdx.x * 256 + threadIdx.x;
    int r = id >> 11, c = id & 2047;
    int t = r / HIDP_, ro = r - t * HIDP_;
    int kb = ro / HBLK_, o = ro - kb * HBLK_;
    if (o >= 683) { F[id] = __float2half(0.f); return; }
    int jb = c >> 8, p = c & 255;
    int i = g_Ji[kb*8 + jb];
    const float* src = t ? wu : wg;
    float s = g_scale[32 + t*8 + i];
    float w = src[((size_t)i * 683 + o) * 256 + p];
    F[id] = __float2half(g_Sg[kb*8 + jb] * tsign(w, s) * s);
}
__global__ void build_d_k(const float* __restrict__ wd, __half* __restrict__ F) {
    int id = blockIdx.x * 256 + threadIdx.x;
    int r = id / HIDP_, c = id - r * HIDP_;
    int jb = c / HBLK_, p = c - jb * HBLK_;
    if (p >= 683) { F[id] = __float2half(0.f); return; }
    int kb = r >> 8, o = r & 255;
    int i = g_Ji[kb*8 + jb];
    float s = g_scale[48 + i];
    float w = wd[((size_t)i * 256 + o) * 683 + p];
    F[id] = __float2half(g_Sg[kb*8 + jb] * tsign(w, s) * s);
}

// ---------------- rmsnorm -> fp16 ----------------
__global__ void rmsnorm_k(const float* __restrict__ x, const float* __restrict__ w,
                          __half* __restrict__ oh) {
    int row = blockIdx.x;
    const float* xr = x + (size_t)row * C_;
    float s = 0.f;
    for (int c = threadIdx.x; c < C_; c += 256) { float v = xr[c]; s += v * v; }
    __shared__ float red[256];
    red[threadIdx.x] = s; __syncthreads();
    for (int st = 128; st > 0; st >>= 1) {
        if (threadIdx.x < st) red[threadIdx.x] += red[threadIdx.x + st];
        __syncthreads();
    }
    float inv = 1.0f / sqrtf(red[0] / (float)C_ + 1e-6f);
    for (int c = threadIdx.x; c < C_; c += 256)
        oh[(size_t)row * C_ + c] = __float2half(xr[c] * inv * w[c]);
}

// ---------------- fp16 single-term GEMM, 128x256 tile ----------------
#define G1_ABYTES 16384
#define G1_STAGE  49152    // A 16KB | B 32KB
#define G1_SMEM   (3 * G1_STAGE)

__device__ __forceinline__ void store2(float* C, size_t i, float x, float y, const float* add) {
    if (add) { const float2 a = *(const float2*)&add[i]; x += a.x; y += a.y; }
    *(float2*)&C[i] = make_float2(x, y);
}
__device__ __forceinline__ void store2(__half* C, size_t i, float x, float y, const float* add) {
    *(__half2*)&C[i] = __floats2half2_rn(x, y);
}

template<typename OutT>
__global__ __launch_bounds__(256, 1) void gemm1_k(
    const __half* __restrict__ A, const __half* __restrict__ B,
    const float* __restrict__ addsrc, OutT* __restrict__ Cm,
    int M, int N, int K)
{
    extern __shared__ __align__(1024) char smem[];
    int tid = threadIdx.x, wid = tid >> 5, lane = tid & 31;
    int wr = wid >> 1, wc = wid & 1;
    int bm = blockIdx.y * 128, bn = blockIdx.x * 256;
    uint32_t sbase = smem_u32(smem);
    int total = K >> 6;

    float acc[2][16][4];
#pragma unroll
    for (int mt = 0; mt < 2; mt++)
#pragma unroll
        for (int nt = 0; nt < 16; nt++)
#pragma unroll
            for (int e = 0; e < 4; e++) acc[mt][nt][e] = 0.f;

    int a_row = ((lane >> 3) & 1) * 8 + (lane & 7);
    int a_kb  = (lane >> 4) * 16;
    int b_n   = ((lane >> 4) & 1) * 8 + (lane & 7);
    int b_kb  = ((lane >> 3) & 1) * 16;

#define ISSUE1(ch) do {                                                       \
        int k0_ = (ch) << 6;                                                  \
        uint32_t stg_ = sbase + ((ch) % 3) * G1_STAGE;                        \
        _Pragma("unroll")                                                     \
        for (int u = 0; u < 4; u++) {                                         \
            int i_ = tid + u * 256;                                           \
            int row_ = i_ >> 3, seg_ = i_ & 7;                                \
            cp16(stg_ + SW128(row_ * 128 + seg_ * 16),                        \
                 A + (size_t)(bm + row_) * K + k0_ + seg_ * 8);               \
        }                                                                     \
        _Pragma("unroll")                                                     \
        for (int u = 0; u < 8; u++) {                                         \
            int i_ = tid + u * 256;                                           \
            int row_ = i_ >> 3, seg_ = i_ & 7;                                \
            cp16(stg_ + G1_ABYTES + SW128(row_ * 128 + seg_ * 16),            \
                 B + (size_t)(bn + row_) * K + k0_ + seg_ * 8);               \
        }                                                                     \
        asm volatile("cp.async.commit_group;" ::: "memory");                  \
    } while (0)

    ISSUE1(0);
    if (total > 1) ISSUE1(1);
    for (int ch = 0; ch < total; ch++) {
        if (ch + 2 < total) {
            ISSUE1(ch + 2);
            asm volatile("cp.async.wait_group 2;" ::: "memory");
        } else if (ch + 1 < total) {
            asm volatile("cp.async.wait_group 1;" ::: "memory");
        } else {
            asm volatile("cp.async.wait_group 0;" ::: "memory");
        }
        __syncthreads();

        uint32_t stg = sbase + (ch % 3) * G1_STAGE;
#pragma unroll
        for (int kk = 0; kk < 4; kk++) {
            uint32_t a[2][4];
#pragma unroll
            for (int mt = 0; mt < 2; mt++) {
                uint32_t byte = (uint32_t)(wr * 32 + mt * 16 + a_row) * 128 + kk * 32 + a_kb;
                ldm_x4(stg + SW128(byte), a[mt][0], a[mt][1], a[mt][2], a[mt][3]);
            }
            uint32_t b[8][4];
#pragma unroll
            for (int np = 0; np < 8; np++) {
                uint32_t byte = (uint32_t)(wc * 128 + np * 16 + b_n) * 128 + kk * 32 + b_kb;
                ldm_x4(stg + G1_ABYTES + SW128(byte), b[np][0], b[np][1], b[np][2], b[np][3]);
            }
#pragma unroll
            for (int mt = 0; mt < 2; mt++)
#pragma unroll
                for (int nt = 0; nt < 16; nt++)
                    mma16816h(acc[mt][nt], a[mt], b[nt >> 1][(nt & 1) * 2],
                              b[nt >> 1][(nt & 1) * 2 + 1]);
        }
        __syncthreads();
    }

#pragma unroll
    for (int mt = 0; mt < 2; mt++)
#pragma unroll
        for (int nt = 0; nt < 16; nt++) {
            int r0 = bm + wr * 32 + mt * 16 + (lane >> 2);
            int c  = bn + wc * 128 + nt * 8 + (lane & 3) * 2;
            size_t i0 = (size_t)r0 * N + c;
            size_t i1 = i0 + (size_t)8 * N;
            store2(Cm, i0, acc[mt][nt][0], acc[mt][nt][1], addsrc);
            store2(Cm, i1, acc[mt][nt][2], acc[mt][nt][3], addsrc);
        }
}

// ---------------- RoPE on merged fp16 QKV (heads 0-15 Q, 16-31 K) ----------------
__global__ void rope_k(__half* __restrict__ x, const float* __restrict__ cosb,
                       const float* __restrict__ sinb) {
    int id = blockIdx.x * 256 + threadIdx.x;    // BT_*2048 pairs
    int m = id >> 11;
    int pi = id & 2047;
    int h = pi >> 6, dp = pi & 63;
    int t = m & (T_ - 1);
    size_t base = (size_t)m * NQKV_ + h * HD_ + 2 * dp;
    __half2 v = *(__half2*)&x[base];
    float xr = __low2float(v), xi = __high2float(v);
    float cc = cosb[t * 64 + dp], ss = sinb[t * 64 + dp];
    *(__half2*)&x[base] = __floats2half2_rn(xr * cc - xi * ss, xr * ss + xi * cc);
}

// ---------------- HMMA flash attention ----------------
// grid (64 bh, 8 qtiles), 256 thr; 128 q-rows/CTA, 64-key tiles; Q in regs.
#define ATT_SMEM 98304     // Q 32K | 2 x (K 16K + V 16K)
__global__ __launch_bounds__(256, 1) void attn_k(
    const __half* __restrict__ qkv, __half* __restrict__ y)
{
    extern __shared__ __align__(1024) char smem[];
    uint32_t sQ = smem_u32(smem);
    int tid = threadIdx.x, wid = tid >> 5, lane = tid & 31;
    int bh = blockIdx.x, qt = blockIdx.y;
    int bb = bh >> 4, h = bh & 15;
    const float sc = 0.08838834764831845f;

    int a_row = ((lane >> 3) & 1) * 8 + (lane & 7);
    int a_kb  = (lane >> 4) * 16;
    int b_n   = ((lane >> 4) & 1) * 8 + (lane & 7);
    int b_kb  = ((lane >> 3) & 1) * 16;
    int v_key = ((lane >> 3) & 1) * 8 + (lane & 7);
    int v_col = ((lane >> 4) & 1) * 8;

    int qrow0 = bb * T_ + qt * 128;   // global row base of this q-tile

    // Q tile 128x128 fp16 (rows 256B, SWK swizzle)
#pragma unroll
    for (int u = 0; u < 8; u++) {
        int i = tid + u * 256;
        int row = i >> 4, seg = i & 15;
        cp16(sQ + SWK(row * 256 + seg * 16),
             qkv + (size_t)(qrow0 + row) * NQKV_ + h * HD_ + seg * 8);
    }
    asm volatile("cp.async.commit_group;" ::: "memory");

    int nkt = 2 * qt + 2;
#define ISSUE_KV(kt_) do {                                                    \
        uint32_t stg_ = sQ + 32768 + ((kt_) & 1) * 32768;                     \
        int kb_ = (kt_) * 64;                                                 \
        _Pragma("unroll")                                                     \
        for (int u = 0; u < 4; u++) {                                         \
            int i_ = tid + u * 256;                                           \
            int row_ = i_ >> 4, seg_ = i_ & 15;                               \
            size_t gr_ = (size_t)(bb * T_ + kb_ + row_) * NQKV_ + h * HD_ + seg_ * 8; \
            uint32_t so_ = SWK(row_ * 256 + seg_ * 16);                       \
            cp16(stg_ + so_, qkv + 2048 + gr_);                               \
            cp16(stg_ + 16384 + so_, qkv + 4096 + gr_);                       \
        }                                                                     \
        asm volatile("cp.async.commit_group;" ::: "memory");                  \
    } while (0)

    ISSUE_KV(0);
    asm volatile("cp.async.wait_group 1;" ::: "memory");   // Q ready
    __syncthreads();

    uint32_t qa[8][4];
#pragma unroll
    for (int kk = 0; kk < 8; kk++) {
        uint32_t byte = (uint32_t)(wid * 16 + a_row) * 256 + kk * 32 + a_kb;
        ldm_x4(sQ + SWK(byte), qa[kk][0], qa[kk][1], qa[kk][2], qa[kk][3]);
    }

    float o[16][4];
#pragma unroll
    for (int nt = 0; nt < 16; nt++)
#pragma unroll
        for (int e = 0; e < 4; e++) o[nt][e] = 0.f;
    float mrun0 = -INFINITY, mrun1 = -INFINITY, lrun0 = 0.f, lrun1 = 0.f;

    int rg0 = qt * 128 + wid * 16 + (lane >> 2);  // row within batch (causal idx)
    int rg1 = rg0 + 8;

    for (int kt = 0; kt < nkt; kt++) {
        if (kt + 1 < nkt) {
            ISSUE_KV(kt + 1);
            asm volatile("cp.async.wait_group 1;" ::: "memory");
        } else {
            asm volatile("cp.async.wait_group 0;" ::: "memory");
        }
        __syncthreads();
        uint32_t sK = sQ + 32768 + (kt & 1) * 32768;
        uint32_t sV = sK + 16384;

        // S = Q K^T  (16 rows x 64 keys per warp)
        float s[8][4];
#pragma unroll
        for (int nt = 0; nt < 8; nt++)
#pragma unroll
            for (int e = 0; e < 4; e++) s[nt][e] = 0.f;
#pragma unroll
        for (int kk = 0; kk < 8; kk++) {
            uint32_t bq[4][4];
#pragma unroll
            for (int np = 0; np < 4; np++) {
                uint32_t byte = (uint32_t)(np * 16 + b_n) * 256 + kk * 32 + b_kb;
                ldm_x4(sK + SWK(byte), bq[np][0], bq[np][1], bq[np][2], bq[np][3]);
            }
#pragma unroll
            for (int nt = 0; nt < 8; nt++)
                mma16816h(s[nt], qa[kk], bq[nt >> 1][(nt & 1) * 2],
                          bq[nt >> 1][(nt & 1) * 2 + 1]);
        }

        // online softmax
        int kb0 = kt * 64;
        bool domask = (kt >= 2 * qt);
        float m0 = -INFINITY, m1 = -INFINITY;
#pragma unroll
        for (int nt = 0; nt < 8; nt++) {
            int k0 = kb0 + nt * 8 + 2 * (lane & 3);
#pragma unroll
            for (int e = 0; e < 4; e++) {
                float sv = s[nt][e] * sc;
                if (domask) {
                    int kc = k0 + (e & 1);
                    int rg = (e < 2) ? rg0 : rg1;
                    if (kc > rg) sv = -1e30f;
                }
                s[nt][e] = sv;
            }
            m0 = fmaxf(m0, fmaxf(s[nt][0], s[nt][1]));
            m1 = fmaxf(m1, fmaxf(s[nt][2], s[nt][3]));
        }
        m0 = fmaxf(m0, __shfl_xor_sync(0xffffffffu, m0, 1));
        m0 = fmaxf(m0, __shfl_xor_sync(0xffffffffu, m0, 2));
        m1 = fmaxf(m1, __shfl_xor_sync(0xffffffffu, m1, 1));
        m1 = fmaxf(m1, __shfl_xor_sync(0xffffffffu, m1, 2));
        float mn0 = fmaxf(mrun0, m0), mn1 = fmaxf(mrun1, m1);
        float al0 = __expf(mrun0 - mn0), al1 = __expf(mrun1 - mn1);
        mrun0 = mn0; mrun1 = mn1;
        float ls0 = 0.f, ls1 = 0.f;
#pragma unroll
        for (int nt = 0; nt < 8; nt++) {
            s[nt][0] = __expf(s[nt][0] - mn0);
            s[nt][1] = __expf(s[nt][1] - mn0);
            s[nt][2] = __expf(s[nt][2] - mn1);
            s[nt][3] = __expf(s[nt][3] - mn1);
            ls0 += s[nt][0] + s[nt][1];
            ls1 += s[nt][2] + s[nt][3];
        }
        ls0 += __shfl_xor_sync(0xffffffffu, ls0, 1);
        ls0 += __shfl_xor_sync(0xffffffffu, ls0, 2);
        ls1 += __shfl_xor_sync(0xffffffffu, ls1, 1);
        ls1 += __shfl_xor_sync(0xffffffffu, ls1, 2);
        lrun0 = lrun0 * al0 + ls0;
        lrun1 = lrun1 * al1 + ls1;
#pragma unroll
        for (int nt = 0; nt < 16; nt++) {
            o[nt][0] *= al0; o[nt][1] *= al0;
            o[nt][2] *= al1; o[nt][3] *= al1;
        }

        // O += P V   (k = 64 keys in 4 steps)
#pragma unroll
        for (int ks = 0; ks < 4; ks++) {
            uint32_t pa[4];
            pa[0] = packh2(s[2*ks][0],   s[2*ks][1]);
            pa[1] = packh2(s[2*ks][2],   s[2*ks][3]);
            pa[2] = packh2(s[2*ks+1][0], s[2*ks+1][1]);
            pa[3] = packh2(s[2*ks+1][2], s[2*ks+1][3]);
#pragma unroll
            for (int nv = 0; nv < 8; nv++) {
                uint32_t r0, r1, r2, r3;
                uint32_t byte = (uint32_t)(ks * 16 + v_key) * 256 + (nv * 16 + v_col) * 2;
                ldm_x4t(sV + SWK(byte), r0, r1, r2, r3);
                mma16816h(o[2*nv],     pa, r0, r1);
                mma16816h(o[2*nv + 1], pa, r2, r3);
            }
        }
        __syncthreads();   // stage consumed; next issue may overwrite
    }

    float il0 = 1.f / lrun0, il1 = 1.f / lrun1;
    size_t row0 = (size_t)bb * T_ + rg0;
    size_t row1 = row0 + 8;
#pragma unroll
    for (int nt = 0; nt < 16; nt++) {
        int c = h * HD_ + nt * 8 + 2 * (lane & 3);
        *(__half2*)&y[row0 * C_ + c] = __floats2half2_rn(o[nt][0] * il0, o[nt][1] * il0);
        *(__half2*)&y[row1 * C_ + c] = __floats2half2_rn(o[nt][2] * il1, o[nt][3] * il1);
    }
}

// ---------------- silu(gate)*up -> fp16 (half2) ----------------
__global__ void siluprod_k(const __half* __restrict__ gu, __half* __restrict__ pr) {
    size_t id = (size_t)blockIdx.x * 256 + threadIdx.x;   // BT_*2752
    size_t row = id / 2752;
    int c2 = (int)(id - row * 2752) * 2;
    size_t base = row * NGU_;
    float2 gv = __half22float2(*(const __half2*)&gu[base + c2]);
    float2 uv = __half22float2(*(const __half2*)&gu[base + HIDP_ + c2]);
    float p0 = gv.x / (1.f + __expf(-gv.x)) * uv.x;
    float p1 = gv.y / (1.f + __expf(-gv.y)) * uv.y;
    *(__half2*)&pr[row * HIDP_ + c2] = __floats2half2_rn(p0, p1);
}

// ---------------- launch ----------------
extern "C" void kernel_launch(void* const* d_in, const int* in_sizes, int n_in,
                              void* d_out, int out_size) {
    const float* x   = (const float*)d_in[0];
    const float* fc  = (const float*)d_in[1];
    const float* fs  = (const float*)d_in[2];
    const float* anw = (const float*)d_in[3];
    const float* fnw = (const float*)d_in[4];
    const float* wq  = (const float*)d_in[5];
    const float* wk  = (const float*)d_in[6];
    const float* wv  = (const float*)d_in[7];
    const float* wo  = (const float*)d_in[8];
    const float* wg  = (const float*)d_in[9];
    const float* wu  = (const float*)d_in[10];
    const float* wd  = (const float*)d_in[11];
    float* out = (float*)d_out;

    __half *Wqkv, *Wo, *Wgu, *Wd, *XN, *Y, *HN, *GU, *PR, *QKV;
    float *Hb;
    cudaGetSymbolAddress((void**)&Wqkv, g_Wqkv);
    cudaGetSymbolAddress((void**)&Wo,   g_Wo);
    cudaGetSymbolAddress((void**)&Wgu,  g_Wgu);
    cudaGetSymbolAddress((void**)&Wd,   g_Wd);
    cudaGetSymbolAddress((void**)&XN,   g_XN);
    cudaGetSymbolAddress((void**)&Y,    g_Y);
    cudaGetSymbolAddress((void**)&HN,   g_HN);
    cudaGetSymbolAddress((void**)&GU,   g_GU);
    cudaGetSymbolAddress((void**)&PR,   g_PR);
    cudaGetSymbolAddress((void**)&QKV,  g_QKV);
    cudaGetSymbolAddress((void**)&Hb,   g_Hb);

    cudaFuncSetAttribute(attn_k, cudaFuncAttributeMaxDynamicSharedMemorySize, ATT_SMEM);
    cudaFuncSetAttribute(gemm1_k<float>, cudaFuncAttributeMaxDynamicSharedMemorySize, G1_SMEM);
    cudaFuncSetAttribute(gemm1_k<__half>, cudaFuncAttributeMaxDynamicSharedMemorySize, G1_SMEM);

    build_tables_k<<<1, 1>>>();

    ScaleSrc ss;
    ss.p[0] = wq; ss.p[1] = wk; ss.p[2] = wv; ss.p[3] = wo;
    ss.p[4] = wg; ss.p[5] = wu; ss.p[6] = wd;
    ss.op[0] = ss.op[1] = ss.op[2] = ss.op[3] = 65536;
    ss.op[4] = ss.op[5] = ss.op[6] = 683 * 256;
    scales_part_k<<<dim3(8, 8, 7), 256>>>(ss);
    scales_fin_k<<<1, 56>>>(ss);

    build_qkv_k<<<(NQKV_ * C_) / 256, 256>>>(wq, wk, wv, Wqkv);
    build_wo_k<<<(C_ * C_) / 256, 256>>>(wo, Wo);
    build_gu_k<<<(NGU_ * C_) / 256, 256>>>(wg, wu, Wgu);
    build_d_k<<<(C_ * HIDP_) / 256, 256>>>(wd, Wd);

    rmsnorm_k<<<BT_, 256>>>(x, anw, XN);

    gemm1_k<__half><<<dim3(NQKV_ / 256, BT_ / 128), 256, G1_SMEM>>>(
        XN, Wqkv, nullptr, QKV, BT_, NQKV_, C_);

    rope_k<<<(BT_ * 2048) / 256, 256>>>(QKV, fc, fs);

    attn_k<<<dim3(64, 8), 256, ATT_SMEM>>>(QKV, Y);

    gemm1_k<float><<<dim3(C_ / 256, BT_ / 128), 256, G1_SMEM>>>(
        Y, Wo, x, Hb, BT_, C_, C_);

    rmsnorm_k<<<BT_, 256>>>(Hb, fnw, HN);

    gemm1_k<__half><<<dim3(NGU_ / 256, BT_ / 128), 256, G1_SMEM>>>(
        HN, Wgu, nullptr, GU, BT_, NGU_, C_);

    siluprod_k<<<(BT_ * 2752) / 256, 256>>>(GU, PR);

    gemm1_k<float><<<dim3(C_ / 256, BT_ / 128), 256, G1_SMEM>>>(
        PR, Wd, Hb, out, BT_, C_, HIDP_);
}